// round 13
// baseline (speedup 1.0000x reference)
#include <cuda_runtime.h>
#include <cuda_fp16.h>
#include <stdint.h>
#include <math.h>

#define BB  2
#define SS  2048
#define EE  1024
#define HH  16
#define HD_ 64
#define FFD 4096
#define MM  (BB*SS)   // 4096

// ---------------- scratch (allocation-free) ----------------
static __device__ __half g_h    [MM*EE];
static __device__ __half g_q    [MM*EE];
static __device__ __half g_kv   [MM*128];     // packed [k|v] per row
static __device__ __half g_att  [MM*EE];
static __device__ float  g_x1   [MM*EE];
static __device__ __half g_hu   [MM*FFD];
// transposed fp16 weights
static __device__ __half g_wqkvT[1152*EE];    // 0-1023 wq, 1024-1087 wk, 1088-1151 wv
static __device__ __half g_woT  [EE*EE];
static __device__ __half g_wguT [2*FFD*EE];   // interleaved: block p = [64 wg | 64 wu]
static __device__ __half g_wdT  [EE*FFD];
static __device__ float  g_bqkv [1152];
static __device__ float  g_bgu  [2*FFD];
static __device__ float2 g_ropetab[SS*32];    // (cos, sin) per (s, j)

// =================== helpers ===================
__device__ __forceinline__ uint32_t smem_u32(const void* p) {
    uint32_t a;
    asm("{ .reg .u64 t; cvta.to.shared.u64 t, %1; cvt.u32.u64 %0, t; }"
        : "=r"(a) : "l"(p));
    return a;
}
__device__ __forceinline__ void cpasync16(uint32_t sp, const void* gp) {
    asm volatile("cp.async.ca.shared.global [%0], [%1], 16;" :: "r"(sp), "l"(gp) : "memory");
}
__device__ __forceinline__ void ldsm4(uint32_t addr, uint32_t& r0, uint32_t& r1,
                                      uint32_t& r2, uint32_t& r3) {
    asm volatile("ldmatrix.sync.aligned.m8n8.x4.shared.b16 {%0,%1,%2,%3}, [%4];"
                 : "=r"(r0), "=r"(r1), "=r"(r2), "=r"(r3) : "r"(addr));
}
__device__ __forceinline__ void ldsm4t(uint32_t addr, uint32_t& r0, uint32_t& r1,
                                       uint32_t& r2, uint32_t& r3) {
    asm volatile("ldmatrix.sync.aligned.m8n8.x4.trans.shared.b16 {%0,%1,%2,%3}, [%4];"
                 : "=r"(r0), "=r"(r1), "=r"(r2), "=r"(r3) : "r"(addr));
}
__device__ __forceinline__ void mma_f16(float* d, const uint32_t* a, const uint32_t* b) {
    asm volatile(
        "mma.sync.aligned.m16n8k16.row.col.f32.f16.f16.f32 "
        "{%0,%1,%2,%3}, {%4,%5,%6,%7}, {%8,%9}, {%0,%1,%2,%3};"
        : "+f"(d[0]), "+f"(d[1]), "+f"(d[2]), "+f"(d[3])
        : "r"(a[0]), "r"(a[1]), "r"(a[2]), "r"(a[3]), "r"(b[0]), "r"(b[1]));
}
__device__ __forceinline__ uint32_t packh2(float a, float b) {
    __half2 h = __floats2half2_rn(a, b);
    return *(uint32_t*)&h;
}

// GEMM smem: per stage {A[128][40] + B[128][40]} halves (pitch 80 B); 3 stages
#define OP_BYTES   10240
#define STAGE_B    (2 * OP_BYTES)     // 20480
#define GEMM_SMEM  (3 * STAGE_B)      // 61440

// =================== fp16 mma.sync GEMM (3-stage, K-chunk 32, 1 sync/chunk) ===========
// C = A[M,K] @ WT[N,K]^T + bias. EPI: 1=+bias+extra(f32)->f32;
// 5=QKV split; 6=fused gelu-gate*up -> hu (tile = [64 gate | 64 up] cols)
template<int EPI>
__global__ void __launch_bounds__(256, 2)
mma_gemm(const __half* __restrict__ A, const __half* __restrict__ WT,
         const float* __restrict__ bias, const void* extra,
         void* __restrict__ Cv, int N, int K) {
    extern __shared__ char dyn[];
    const uint32_t smem_base = smem_u32(dyn);

    const int tid  = threadIdx.x;
    const int lane = tid & 31;
    const int warp = tid >> 5;
    const int wr = warp & 1;
    const int wc = warp >> 1;
    const int row0 = blockIdx.y * 128, col0 = blockIdx.x * 128;
    const int rp = lane >> 2;
    const int cp = lane & 3;

    const uint32_t a_lm = (uint32_t)((wr*64 + (lane & 15)) * 80 + ((lane >> 4) & 1) * 16);
    const uint32_t b_lm = (uint32_t)((wc*32 + (lane & 7) + ((lane >> 4) & 1) * 8) * 80
                                     + ((lane >> 3) & 1) * 16);

    float acc[4][4][4];
#pragma unroll
    for (int i = 0; i < 4; i++)
#pragma unroll
        for (int j = 0; j < 4; j++)
#pragma unroll
            for (int q = 0; q < 4; q++) acc[i][j][q] = 0.f;

    auto issue = [&](int buf, int kb) {
        uint32_t as = smem_base + (uint32_t)buf * STAGE_B;
        uint32_t bs = as + OP_BYTES;
#pragma unroll
        for (int i = 0; i < 2; i++) {
            int f = tid + i * 256;
            int r = f >> 2, c = f & 3;
            cpasync16(as + (uint32_t)(r * 80 + c * 16),
                      A + (size_t)(row0 + r) * K + kb + c * 8);
        }
#pragma unroll
        for (int i = 0; i < 2; i++) {
            int f = tid + i * 256;
            int r = f >> 2, c = f & 3;
            cpasync16(bs + (uint32_t)(r * 80 + c * 16),
                      WT + (size_t)(col0 + r) * K + kb + c * 8);
        }
        asm volatile("cp.async.commit_group;" ::: "memory");
    };

    auto compute = [&](int buf) {
        const uint32_t as = smem_base + (uint32_t)buf * STAGE_B + a_lm;
        const uint32_t bs = smem_base + (uint32_t)buf * STAGE_B + OP_BYTES + b_lm;
#pragma unroll
        for (int ks = 0; ks < 2; ks++) {
            uint32_t af[4][4];
#pragma unroll
            for (int mt = 0; mt < 4; mt++)
                ldsm4(as + (uint32_t)(mt * 1280 + ks * 32),
                      af[mt][0], af[mt][1], af[mt][2], af[mt][3]);
            uint32_t bf[4][2];
            ldsm4(bs + (uint32_t)(ks * 32),        bf[0][0], bf[0][1], bf[1][0], bf[1][1]);
            ldsm4(bs + (uint32_t)(1280 + ks * 32), bf[2][0], bf[2][1], bf[3][0], bf[3][1]);
#pragma unroll
            for (int mt = 0; mt < 4; mt++)
#pragma unroll
                for (int nt = 0; nt < 4; nt++)
                    mma_f16(acc[mt][nt], af[mt], bf[nt]);
        }
    };

    const int nk = K >> 5;
    issue(0, 0); issue(1, 32);
    int cur = 0, nxt = 2;
    for (int kt = 0; kt < nk; kt++) {
        if (kt == nk - 1) asm volatile("cp.async.wait_group 0;" ::: "memory");
        else              asm volatile("cp.async.wait_group 1;" ::: "memory");
        __syncthreads();
        if (kt + 2 < nk) { issue(nxt, (kt + 2) << 5); nxt = (nxt == 2) ? 0 : nxt + 1; }
        compute(cur);
        cur = (cur == 2) ? 0 : cur + 1;
    }

    // ---------------- epilogue ----------------
    if (EPI == 6) {
        float* smg = (float*)dyn;                // 128 x 72 fp32
        __syncthreads();
        if (wc < 2) {
#pragma unroll
            for (int mt = 0; mt < 4; mt++)
#pragma unroll
                for (int nt = 0; nt < 4; nt++) {
                    int rl = wr*64 + mt*16 + rp;
                    int cl = wc*32 + nt*8 + 2*cp;
#pragma unroll
                    for (int half_ = 0; half_ < 2; half_++) {
                        int r = rl + half_ * 8;
                        float v0 = acc[mt][nt][half_*2 + 0] + bias[col0 + cl];
                        float v1 = acc[mt][nt][half_*2 + 1] + bias[col0 + cl + 1];
                        v0 = 0.5f * v0 * (1.0f + erff(v0 * 0.7071067811865476f));
                        v1 = 0.5f * v1 * (1.0f + erff(v1 * 0.7071067811865476f));
                        *(float2*)&smg[r * 72 + cl] = make_float2(v0, v1);
                    }
                }
        }
        __syncthreads();
        if (wc >= 2) {
            __half* hu = (__half*)Cv;
            const int p64 = (col0 >> 7) * 64;
#pragma unroll
            for (int mt = 0; mt < 4; mt++)
#pragma unroll
                for (int nt = 0; nt < 4; nt++) {
                    int rl = wr*64 + mt*16 + rp;
                    int cl = (wc - 2)*32 + nt*8 + 2*cp;
#pragma unroll
                    for (int half_ = 0; half_ < 2; half_++) {
                        int r = rl + half_ * 8;
                        float v0 = acc[mt][nt][half_*2 + 0] + bias[col0 + 64 + cl];
                        float v1 = acc[mt][nt][half_*2 + 1] + bias[col0 + 64 + cl + 1];
                        float2 g = *(const float2*)&smg[r * 72 + cl];
                        *(__half2*)&hu[(size_t)(row0 + r) * FFD + p64 + cl] =
                            __floats2half2_rn(v0 * g.x, v1 * g.y);
                    }
                }
        }
        return;
    }

#pragma unroll
    for (int mt = 0; mt < 4; mt++) {
#pragma unroll
        for (int nt = 0; nt < 4; nt++) {
            int row = row0 + wr*64 + mt*16 + rp;
            int col = col0 + wc*32 + nt*8 + 2*cp;
#pragma unroll
            for (int half_ = 0; half_ < 2; half_++) {
                int r = row + half_ * 8;
                float v0 = acc[mt][nt][half_*2 + 0] + bias[col];
                float v1 = acc[mt][nt][half_*2 + 1] + bias[col + 1];
                if (EPI == 5) {
                    __half2 o = __floats2half2_rn(v0, v1);
                    if (col < 1024)
                        *(__half2*)((__half*)Cv + (size_t)r * N + col) = o;
                    else
                        *(__half2*)((__half*)extra + (size_t)r * 128 + (col - 1024)) = o;
                } else { // EPI 1
                    size_t gi = (size_t)r * N + col;
                    float2 e = *(const float2*)((const float*)extra + gi);
                    *(float2*)((float*)Cv + gi) = make_float2(v0 + e.x, v1 + e.y);
                }
            }
        }
    }
}

// ---------------- fused weight prep: ALL transposes + rope table in one launch --------
#define WPREP_BLOCKS 3616
__global__ void __launch_bounds__(256)
wprep_kernel(const float* __restrict__ wq, const float* __restrict__ wk,
             const float* __restrict__ wv, const float* __restrict__ wo,
             const float* __restrict__ wg, const float* __restrict__ wu,
             const float* __restrict__ wd,
             __half* __restrict__ wqkvT, __half* __restrict__ woT,
             __half* __restrict__ wguT, __half* __restrict__ wdT,
             const float* __restrict__ bq, const float* __restrict__ bk,
             const float* __restrict__ bv, const float* __restrict__ bg,
             const float* __restrict__ bu,
             float* __restrict__ bqkv, float* __restrict__ bgu,
             float2* __restrict__ ropetab) {
    const int bidx = blockIdx.x;
    const int tid = threadIdx.x;

    if (bidx == 0) {
#pragma unroll
        for (int j = 0; j < 5; j++) {
            int i = tid + j * 256;
            if (i < 1152)
                bqkv[i] = (i < 1024) ? bq[i] : (i < 1088 ? bk[i - 1024] : bv[i - 1088]);
        }
    }
    if (bidx == 1) {
#pragma unroll
        for (int j = 0; j < 32; j++) {
            int i = tid + j * 256;          // 0..8191
            int p = i >> 7, r = i & 127;
            bgu[i] = (r < 64) ? bg[p*64 + r] : bu[p*64 + (r - 64)];
        }
    }
    if (bidx >= 2 && bidx < 258) {          // rope table: 256 entries per block
        int e = (bidx - 2) * 256 + tid;     // 0..65535
        int s = e >> 5, j = e & 31;
        float inv = exp2f((float)j * -0.41524101186092029f);   // -log2(10000)/32
        float c, sn;
        sincosf((float)s * inv, &sn, &c);
        ropetab[e] = make_float2(c, sn);
    }

    const float* W; __half* WT; int K, N, t, nbase;
    if      (bidx < 256)  { W = wq; WT = wqkvT;           K = EE;  N = EE;  t = bidx;        }
    else if (bidx < 272)  { W = wk; WT = wqkvT + 1024*EE; K = EE;  N = 64;  t = bidx - 256;  }
    else if (bidx < 288)  { W = wv; WT = wqkvT + 1088*EE; K = EE;  N = 64;  t = bidx - 272;  }
    else if (bidx < 544)  { W = wo; WT = woT;             K = EE;  N = EE;  t = bidx - 288;  }
    else if (bidx < 1568) { W = wg; WT = wguT;            K = EE;  N = FFD; t = bidx - 544;  }
    else if (bidx < 2592) { W = wu; WT = wguT;            K = EE;  N = FFD; t = bidx - 1568; }
    else                  { W = wd; WT = wdT;             K = FFD; N = EE;  t = bidx - 2592; }

    const int tilesX = N >> 6;
    const int nb = (t % tilesX) * 64, kb = (t / tilesX) * 64;
    if (bidx >= 544 && bidx < 1568)       nbase = (nb >> 6) * 128;        // gate half
    else if (bidx >= 1568 && bidx < 2592) nbase = (nb >> 6) * 128 + 64;   // up half
    else                                   nbase = nb;

    __shared__ float sm[64][65];
    const int x = tid & 15, y = tid >> 4;
#pragma unroll
    for (int j = 0; j < 4; j++) {
        int r = y + j * 16;
        float4 v = *(const float4*)&W[(size_t)(kb + r) * N + nb + x * 4];
        sm[x*4 + 0][r] = v.x; sm[x*4 + 1][r] = v.y;
        sm[x*4 + 2][r] = v.z; sm[x*4 + 3][r] = v.w;
    }
    __syncthreads();
    const int lane = tid & 31, w = tid >> 5;
#pragma unroll
    for (int j = 0; j < 8; j++) {
        int n = w * 8 + j;
        __half2 h2 = __floats2half2_rn(sm[n][lane*2], sm[n][lane*2 + 1]);
        *(uint32_t*)&WT[(size_t)(nbase + n) * K + kb + lane*2] = *(uint32_t*)&h2;
    }
}

// ---------------- rmsnorm (fp16 output) ----------------
__global__ void rmsnorm_kernel(const float* __restrict__ x, const float* __restrict__ g,
                               __half* __restrict__ out) {
    int row = blockIdx.x;
    const float* xr = x + (size_t)row * EE;
    float v[4];
    float s = 0.f;
#pragma unroll
    for (int i = 0; i < 4; i++) { v[i] = xr[threadIdx.x + i*256]; s += v[i]*v[i]; }
    __shared__ float red[8];
#pragma unroll
    for (int o = 16; o > 0; o >>= 1) s += __shfl_xor_sync(0xffffffffu, s, o);
    if ((threadIdx.x & 31) == 0) red[threadIdx.x >> 5] = s;
    __syncthreads();
    if (threadIdx.x < 8) {
        float t = red[threadIdx.x];
#pragma unroll
        for (int o = 4; o > 0; o >>= 1) t += __shfl_xor_sync(0xffu, t, o);
        if (threadIdx.x == 0) red[0] = t;
    }
    __syncthreads();
    float ms = red[0] * (1.0f / EE);
    float r  = rsqrtf(ms + 1.1920929e-7f);
#pragma unroll
    for (int i = 0; i < 4; i++) {
        int c = threadIdx.x + i*256;
        out[(size_t)row*EE + c] = __float2half_rn(v[i] * r * g[c]);
    }
}

// ---------------- fused RoPE via table ----------------
#define ROPE_QT (MM*HH*32)
#define ROPE_TOT (ROPE_QT + MM*32)
__global__ void rope_all(__half* __restrict__ q, __half* __restrict__ kv,
                         const float2* __restrict__ tab) {
    int idx = blockIdx.x * blockDim.x + threadIdx.x;
    if (idx >= ROPE_TOT) return;
    __half* t; int nH, rowMul; float scale;
    if (idx < ROPE_QT) { t = q;  nH = HH; rowMul = 1024; scale = 0.125f; }
    else               { t = kv; nH = 1;  rowMul = 128;  scale = 1.0f; idx -= ROPE_QT; }
    int j    = idx & 31;
    int rest = idx >> 5;
    int h    = rest % nH;
    int row  = rest / nH;
    int s    = row % SS;
    float2 cs = __ldg(&tab[s * 32 + j]);
    size_t base = (size_t)row * rowMul + h * 64;
    float t1 = __half2float(t[base + j]), t2 = __half2float(t[base + 32 + j]);
    t[base + j]      = __float2half_rn((t1*cs.x - t2*cs.y) * scale);
    t[base + 32 + j] = __float2half_rn((t1*cs.y + t2*cs.x) * scale);
}

// ---------------- Flash attention, fp16 m16n8k16 (MQA, causal, HD=64) ----------------
// 64-row Q tiles; kv packed row stride 128: k at +0, v at +64
#define ATT_SMEM 46080
__global__ void __launch_bounds__(128)
attn_mma(const __half* __restrict__ q, const __half* __restrict__ kv,
         __half* __restrict__ out) {
    extern __shared__ char smc[];
    const uint32_t sb = smem_u32(smc);
    const int tid = threadIdx.x, lane = tid & 31, w = tid >> 5;
    const int bh = blockIdx.y, b = bh >> 4, h = bh & 15;
    const int qb = (int)(gridDim.x - 1 - blockIdx.x);
    const int rp = lane >> 2, cp = lane & 3;

    const uint32_t qs = sb;
    const uint32_t a_lm = (uint32_t)((w*16 + (lane & 15)) * 144 + ((lane >> 4) & 1) * 16);
    const uint32_t b_lm = (uint32_t)(((lane & 7) + ((lane >> 4) & 1) * 8) * 144
                                     + ((lane >> 3) & 1) * 16);
    const uint32_t v_lm = (uint32_t)(((lane & 7) + ((lane >> 3) & 1) * 8) * 144
                                     + ((lane >> 4) & 1) * 16);

    const __half* qg = q + ((size_t)(b*SS + qb*64)) * 1024 + h*64;
#pragma unroll
    for (int i = 0; i < 4; i++) {
        int f = tid + i * 128;
        int r = f >> 3, c = f & 7;
        cpasync16(qs + (uint32_t)(r * 144 + c * 16), qg + (size_t)r * 1024 + c * 8);
    }
    const __half* kg = kv + (size_t)(b*SS) * 128;
    const __half* vg = kg + 64;
    auto issue_kv = [&](int buf, int kb) {
        uint32_t ksm = sb + 9216u + (uint32_t)buf * 18432u;
        uint32_t vsm = ksm + 9216u;
#pragma unroll
        for (int i = 0; i < 4; i++) {
            int f = tid + i * 128;
            int r = f >> 3, c = f & 7;
            size_t gof = (size_t)(kb*64 + r) * 128 + c * 8;
            cpasync16(ksm + (uint32_t)(r * 144 + c * 16), kg + gof);
            cpasync16(vsm + (uint32_t)(r * 144 + c * 16), vg + gof);
        }
        asm volatile("cp.async.commit_group;" ::: "memory");
    };
    issue_kv(0, 0);

    float o[8][4];
#pragma unroll
    for (int nt = 0; nt < 8; nt++)
#pragma unroll
        for (int j = 0; j < 4; j++) o[nt][j] = 0.f;
    float m0 = -1e30f, m1 = -1e30f, l0 = 0.f, l1 = 0.f;

    for (int kb = 0; kb <= qb; kb++) {
        int buf = kb & 1;
        if (kb < qb) {
            issue_kv(buf ^ 1, kb + 1);
            asm volatile("cp.async.wait_group 1;" ::: "memory");
        } else {
            asm volatile("cp.async.wait_group 0;" ::: "memory");
        }
        __syncthreads();
        const uint32_t ksm = sb + 9216u + (uint32_t)buf * 18432u;
        const uint32_t vsm = ksm + 9216u;

        float s[8][4];
#pragma unroll
        for (int nt = 0; nt < 8; nt++)
#pragma unroll
            for (int j = 0; j < 4; j++) s[nt][j] = 0.f;
#pragma unroll
        for (int ks = 0; ks < 4; ks++) {
            uint32_t af[4];
            ldsm4(qs + a_lm + (uint32_t)(ks * 32), af[0], af[1], af[2], af[3]);
#pragma unroll
            for (int p2 = 0; p2 < 4; p2++) {
                uint32_t bf[4];
                ldsm4(ksm + b_lm + (uint32_t)(p2 * 16 * 144 + ks * 32),
                      bf[0], bf[1], bf[2], bf[3]);
                mma_f16(s[p2*2],     af, &bf[0]);
                mma_f16(s[p2*2 + 1], af, &bf[2]);
            }
        }

        if (kb == qb) {
#pragma unroll
            for (int nt = 0; nt < 8; nt++) {
                int key0 = nt*8 + 2*cp;
                int r0 = w*16 + rp, r1 = r0 + 8;
                if (key0     > r0) s[nt][0] = -1e30f;
                if (key0 + 1 > r0) s[nt][1] = -1e30f;
                if (key0     > r1) s[nt][2] = -1e30f;
                if (key0 + 1 > r1) s[nt][3] = -1e30f;
            }
        }

        float mx0 = -1e30f, mx1 = -1e30f;
#pragma unroll
        for (int nt = 0; nt < 8; nt++) {
            mx0 = fmaxf(mx0, fmaxf(s[nt][0], s[nt][1]));
            mx1 = fmaxf(mx1, fmaxf(s[nt][2], s[nt][3]));
        }
        mx0 = fmaxf(mx0, __shfl_xor_sync(0xffffffffu, mx0, 1, 4));
        mx0 = fmaxf(mx0, __shfl_xor_sync(0xffffffffu, mx0, 2, 4));
        mx1 = fmaxf(mx1, __shfl_xor_sync(0xffffffffu, mx1, 1, 4));
        mx1 = fmaxf(mx1, __shfl_xor_sync(0xffffffffu, mx1, 2, 4));
        float mn0 = fmaxf(m0, mx0), mn1 = fmaxf(m1, mx1);
        float al0 = __expf(m0 - mn0), al1 = __expf(m1 - mn1);
        float sum0 = 0.f, sum1 = 0.f;
        uint32_t ph[8][2];
#pragma unroll
        for (int nt = 0; nt < 8; nt++) {
            float e0 = __expf(s[nt][0] - mn0);
            float e1 = __expf(s[nt][1] - mn0);
            float e2 = __expf(s[nt][2] - mn1);
            float e3 = __expf(s[nt][3] - mn1);
            sum0 += e0 + e1; sum1 += e2 + e3;
            ph[nt][0] = packh2(e0, e1);
            ph[nt][1] = packh2(e2, e3);
        }
        sum0 += __shfl_xor_sync(0xffffffffu, sum0, 1, 4);
        sum0 += __shfl_xor_sync(0xffffffffu, sum0, 2, 4);
        sum1 += __shfl_xor_sync(0xffffffffu, sum1, 1, 4);
        sum1 += __shfl_xor_sync(0xffffffffu, sum1, 2, 4);
        l0 = l0 * al0 + sum0; l1 = l1 * al1 + sum1;
        m0 = mn0; m1 = mn1;
#pragma unroll
        for (int nt = 0; nt < 8; nt++) {
            o[nt][0] *= al0; o[nt][1] *= al0;
            o[nt][2] *= al1; o[nt][3] *= al1;
        }

#pragma unroll
        for (int kt = 0; kt < 4; kt++) {
            uint32_t pa[4] = { ph[2*kt][0], ph[2*kt][1], ph[2*kt+1][0], ph[2*kt+1][1] };
#pragma unroll
            for (int np = 0; np < 4; np++) {
                uint32_t bf[4];
                ldsm4t(vsm + v_lm + (uint32_t)(kt * 16 * 144 + np * 32),
                       bf[0], bf[1], bf[2], bf[3]);
                mma_f16(o[np*2],     pa, &bf[0]);
                mma_f16(o[np*2 + 1], pa, &bf[2]);
            }
        }
        __syncthreads();
    }

    float inv0 = 1.0f / l0, inv1 = 1.0f / l1;
    const int r0 = b*SS + qb*64 + w*16 + rp;
#pragma unroll
    for (int nt = 0; nt < 8; nt++) {
        int d = h*64 + nt*8 + 2*cp;
        *(__half2*)&out[(size_t)r0 * 1024 + d] =
            __floats2half2_rn(o[nt][0] * inv0, o[nt][1] * inv0);
        *(__half2*)&out[(size_t)(r0 + 8) * 1024 + d] =
            __floats2half2_rn(o[nt][2] * inv1, o[nt][3] * inv1);
    }
}

// ---------------- launch ----------------
extern "C" void kernel_launch(void* const* d_in, const int* in_sizes, int n_in,
                              void* d_out, int out_size) {
    const float* x  = (const float*)d_in[0];
    const float* wq = (const float*)d_in[1];
    const float* bq = (const float*)d_in[2];
    const float* wk = (const float*)d_in[3];
    const float* bk = (const float*)d_in[4];
    const float* wv = (const float*)d_in[5];
    const float* bv = (const float*)d_in[6];
    const float* wo = (const float*)d_in[7];
    const float* bo = (const float*)d_in[8];
    const float* wg = (const float*)d_in[9];
    const float* bg = (const float*)d_in[10];
    const float* wu = (const float*)d_in[11];
    const float* bu = (const float*)d_in[12];
    const float* wd = (const float*)d_in[13];
    const float* bd = (const float*)d_in[14];
    const float* g1 = (const float*)d_in[15];
    const float* g2 = (const float*)d_in[16];
    float* out = (float*)d_out;

    __half *h, *qb_, *kv, *att, *hu;
    __half *wqkvT, *woT, *wguT, *wdT;
    float *x1, *bqkv, *bgu;
    float2* ropetab;
    cudaGetSymbolAddress((void**)&h,       g_h);
    cudaGetSymbolAddress((void**)&qb_,     g_q);
    cudaGetSymbolAddress((void**)&kv,      g_kv);
    cudaGetSymbolAddress((void**)&att,     g_att);
    cudaGetSymbolAddress((void**)&x1,      g_x1);
    cudaGetSymbolAddress((void**)&hu,      g_hu);
    cudaGetSymbolAddress((void**)&wqkvT,   g_wqkvT);
    cudaGetSymbolAddress((void**)&woT,     g_woT);
    cudaGetSymbolAddress((void**)&wguT,    g_wguT);
    cudaGetSymbolAddress((void**)&wdT,     g_wdT);
    cudaGetSymbolAddress((void**)&bqkv,    g_bqkv);
    cudaGetSymbolAddress((void**)&bgu,     g_bgu);
    cudaGetSymbolAddress((void**)&ropetab, g_ropetab);

    cudaFuncSetAttribute(mma_gemm<1>, cudaFuncAttributeMaxDynamicSharedMemorySize, GEMM_SMEM);
    cudaFuncSetAttribute(mma_gemm<5>, cudaFuncAttributeMaxDynamicSharedMemorySize, GEMM_SMEM);
    cudaFuncSetAttribute(mma_gemm<6>, cudaFuncAttributeMaxDynamicSharedMemorySize, GEMM_SMEM);
    cudaFuncSetAttribute(attn_mma,    cudaFuncAttributeMaxDynamicSharedMemorySize, ATT_SMEM);

    // 0) fused weight prep (single launch: transposes + biases + rope table)
    wprep_kernel<<<WPREP_BLOCKS, 256>>>(wq, wk, wv, wo, wg, wu, wd,
                                        wqkvT, woT, wguT, wdT,
                                        bq, bk, bv, bg, bu, bqkv, bgu, ropetab);
    // 1) rmsnorm(x, g1) -> h (fp16)
    rmsnorm_kernel<<<MM, 256>>>(x, g1, h);
    // 2) fused QKV projection
    mma_gemm<5><<<dim3(1152/128, MM/128), 256, GEMM_SMEM>>>(h, wqkvT, bqkv, kv, qb_, EE, EE);
    // 3) fused RoPE (table-driven)
    rope_all<<<(ROPE_TOT + 255)/256, 256>>>(qb_, kv, ropetab);
    // 4) attention (64-row Q tiles)
    attn_mma<<<dim3(SS/64, BB*HH), 128, ATT_SMEM>>>(qb_, kv, att);
    // 5) o-proj + residual(x) -> x1 (fp32)
    mma_gemm<1><<<dim3(EE/128, MM/128), 256, GEMM_SMEM>>>(att, woT, bo, x, x1, EE, EE);
    // 6) rmsnorm(x1, g2) -> h (fp16)
    rmsnorm_kernel<<<MM, 256>>>(x1, g2, h);
    // 7+8) fused FFN: hu = fp16(gelu(h@wg+bg) * (h@wu+bu))
    mma_gemm<6><<<dim3(2*FFD/128, MM/128), 256, GEMM_SMEM>>>(h, wguT, bgu, nullptr, hu, 2*FFD, EE);
    // 9) out = hu@wd + bd + x1 (fp32)
    mma_gemm<1><<<dim3(EE/128, MM/128), 256, GEMM_SMEM>>>(hu, wdT, bd, x1, out, EE, FFD);
}

// round 14
// speedup vs baseline: 1.0012x; 1.0012x over previous
#include <cuda_runtime.h>
#include <cuda_fp16.h>
#include <stdint.h>
#include <math.h>

#define BB  2
#define SS  2048
#define EE  1024
#define HH  16
#define HD_ 64
#define FFD 4096
#define MM  (BB*SS)   // 4096

// ---------------- scratch (allocation-free) ----------------
static __device__ __half g_h    [MM*EE];
static __device__ __half g_q    [MM*EE];      // q, RoPE'd, head-dim permuted
static __device__ __half g_kv   [MM*128];     // packed [k(permuted,roped) | v]
static __device__ __half g_att  [MM*EE];
static __device__ float  g_x1   [MM*EE];
static __device__ __half g_hu   [MM*FFD];
// transposed fp16 weights
static __device__ __half g_wqkvT[1152*EE];    // 0-1023 wq(perm), 1024-1087 wk(perm), 1088-1151 wv
static __device__ __half g_woT  [EE*EE];
static __device__ __half g_wguT [2*FFD*EE];   // interleaved: block p = [64 wg | 64 wu]
static __device__ __half g_wdT  [EE*FFD];
static __device__ float  g_bqkv [1152];       // permuted q/k bias
static __device__ float  g_bgu  [2*FFD];
static __device__ float2 g_ropetab[SS*32];    // (cos, sin) per (s, j)

// =================== helpers ===================
__device__ __forceinline__ uint32_t smem_u32(const void* p) {
    uint32_t a;
    asm("{ .reg .u64 t; cvta.to.shared.u64 t, %1; cvt.u32.u64 %0, t; }"
        : "=r"(a) : "l"(p));
    return a;
}
__device__ __forceinline__ void cpasync16(uint32_t sp, const void* gp) {
    asm volatile("cp.async.ca.shared.global [%0], [%1], 16;" :: "r"(sp), "l"(gp) : "memory");
}
__device__ __forceinline__ void ldsm4(uint32_t addr, uint32_t& r0, uint32_t& r1,
                                      uint32_t& r2, uint32_t& r3) {
    asm volatile("ldmatrix.sync.aligned.m8n8.x4.shared.b16 {%0,%1,%2,%3}, [%4];"
                 : "=r"(r0), "=r"(r1), "=r"(r2), "=r"(r3) : "r"(addr));
}
__device__ __forceinline__ void ldsm4t(uint32_t addr, uint32_t& r0, uint32_t& r1,
                                       uint32_t& r2, uint32_t& r3) {
    asm volatile("ldmatrix.sync.aligned.m8n8.x4.trans.shared.b16 {%0,%1,%2,%3}, [%4];"
                 : "=r"(r0), "=r"(r1), "=r"(r2), "=r"(r3) : "r"(addr));
}
__device__ __forceinline__ void mma_f16(float* d, const uint32_t* a, const uint32_t* b) {
    asm volatile(
        "mma.sync.aligned.m16n8k16.row.col.f32.f16.f16.f32 "
        "{%0,%1,%2,%3}, {%4,%5,%6,%7}, {%8,%9}, {%0,%1,%2,%3};"
        : "+f"(d[0]), "+f"(d[1]), "+f"(d[2]), "+f"(d[3])
        : "r"(a[0]), "r"(a[1]), "r"(a[2]), "r"(a[3]), "r"(b[0]), "r"(b[1]));
}
__device__ __forceinline__ uint32_t packh2(float a, float b) {
    __half2 h = __floats2half2_rn(a, b);
    return *(uint32_t*)&h;
}

// GEMM smem: per stage {A[128][40] + B[128][40]} halves (pitch 80 B); 3 stages
#define OP_BYTES   10240
#define STAGE_B    (2 * OP_BYTES)     // 20480
#define GEMM_SMEM  (3 * STAGE_B)      // 61440

// =================== fp16 mma.sync GEMM (3-stage, K-chunk 32, 1 sync/chunk) ===========
// C = A[M,K] @ WT[N,K]^T + bias. EPI: 1=+bias+extra(f32)->f32;
// 5=QKV split + fused RoPE (q/k cols rotated via table); 6=fused gelu-gate*up -> hu
template<int EPI>
__global__ void __launch_bounds__(256, 2)
mma_gemm(const __half* __restrict__ A, const __half* __restrict__ WT,
         const float* __restrict__ bias, const void* extra,
         void* __restrict__ Cv, int N, int K, const float2* __restrict__ rope) {
    extern __shared__ char dyn[];
    const uint32_t smem_base = smem_u32(dyn);

    const int tid  = threadIdx.x;
    const int lane = tid & 31;
    const int warp = tid >> 5;
    const int wr = warp & 1;
    const int wc = warp >> 1;
    const int row0 = blockIdx.y * 128, col0 = blockIdx.x * 128;
    const int rp = lane >> 2;
    const int cp = lane & 3;

    const uint32_t a_lm = (uint32_t)((wr*64 + (lane & 15)) * 80 + ((lane >> 4) & 1) * 16);
    const uint32_t b_lm = (uint32_t)((wc*32 + (lane & 7) + ((lane >> 4) & 1) * 8) * 80
                                     + ((lane >> 3) & 1) * 16);

    float acc[4][4][4];
#pragma unroll
    for (int i = 0; i < 4; i++)
#pragma unroll
        for (int j = 0; j < 4; j++)
#pragma unroll
            for (int q = 0; q < 4; q++) acc[i][j][q] = 0.f;

    auto issue = [&](int buf, int kb) {
        uint32_t as = smem_base + (uint32_t)buf * STAGE_B;
        uint32_t bs = as + OP_BYTES;
#pragma unroll
        for (int i = 0; i < 2; i++) {
            int f = tid + i * 256;
            int r = f >> 2, c = f & 3;
            cpasync16(as + (uint32_t)(r * 80 + c * 16),
                      A + (size_t)(row0 + r) * K + kb + c * 8);
        }
#pragma unroll
        for (int i = 0; i < 2; i++) {
            int f = tid + i * 256;
            int r = f >> 2, c = f & 3;
            cpasync16(bs + (uint32_t)(r * 80 + c * 16),
                      WT + (size_t)(col0 + r) * K + kb + c * 8);
        }
        asm volatile("cp.async.commit_group;" ::: "memory");
    };

    auto compute = [&](int buf) {
        const uint32_t as = smem_base + (uint32_t)buf * STAGE_B + a_lm;
        const uint32_t bs = smem_base + (uint32_t)buf * STAGE_B + OP_BYTES + b_lm;
#pragma unroll
        for (int ks = 0; ks < 2; ks++) {
            uint32_t af[4][4];
#pragma unroll
            for (int mt = 0; mt < 4; mt++)
                ldsm4(as + (uint32_t)(mt * 1280 + ks * 32),
                      af[mt][0], af[mt][1], af[mt][2], af[mt][3]);
            uint32_t bf[4][2];
            ldsm4(bs + (uint32_t)(ks * 32),        bf[0][0], bf[0][1], bf[1][0], bf[1][1]);
            ldsm4(bs + (uint32_t)(1280 + ks * 32), bf[2][0], bf[2][1], bf[3][0], bf[3][1]);
#pragma unroll
            for (int mt = 0; mt < 4; mt++)
#pragma unroll
                for (int nt = 0; nt < 4; nt++)
                    mma_f16(acc[mt][nt], af[mt], bf[nt]);
        }
    };

    const int nk = K >> 5;
    issue(0, 0); issue(1, 32);
    int cur = 0, nxt = 2;
    for (int kt = 0; kt < nk; kt++) {
        if (kt == nk - 1) asm volatile("cp.async.wait_group 0;" ::: "memory");
        else              asm volatile("cp.async.wait_group 1;" ::: "memory");
        __syncthreads();
        if (kt + 2 < nk) { issue(nxt, (kt + 2) << 5); nxt = (nxt == 2) ? 0 : nxt + 1; }
        compute(cur);
        cur = (cur == 2) ? 0 : cur + 1;
    }

    // ---------------- epilogue ----------------
    if (EPI == 6) {
        float* smg = (float*)dyn;                // 128 x 72 fp32
        __syncthreads();
        if (wc < 2) {
#pragma unroll
            for (int mt = 0; mt < 4; mt++)
#pragma unroll
                for (int nt = 0; nt < 4; nt++) {
                    int rl = wr*64 + mt*16 + rp;
                    int cl = wc*32 + nt*8 + 2*cp;
#pragma unroll
                    for (int half_ = 0; half_ < 2; half_++) {
                        int r = rl + half_ * 8;
                        float v0 = acc[mt][nt][half_*2 + 0] + bias[col0 + cl];
                        float v1 = acc[mt][nt][half_*2 + 1] + bias[col0 + cl + 1];
                        v0 = 0.5f * v0 * (1.0f + erff(v0 * 0.7071067811865476f));
                        v1 = 0.5f * v1 * (1.0f + erff(v1 * 0.7071067811865476f));
                        *(float2*)&smg[r * 72 + cl] = make_float2(v0, v1);
                    }
                }
        }
        __syncthreads();
        if (wc >= 2) {
            __half* hu = (__half*)Cv;
            const int p64 = (col0 >> 7) * 64;
#pragma unroll
            for (int mt = 0; mt < 4; mt++)
#pragma unroll
                for (int nt = 0; nt < 4; nt++) {
                    int rl = wr*64 + mt*16 + rp;
                    int cl = (wc - 2)*32 + nt*8 + 2*cp;
#pragma unroll
                    for (int half_ = 0; half_ < 2; half_++) {
                        int r = rl + half_ * 8;
                        float v0 = acc[mt][nt][half_*2 + 0] + bias[col0 + 64 + cl];
                        float v1 = acc[mt][nt][half_*2 + 1] + bias[col0 + 64 + cl + 1];
                        float2 g = *(const float2*)&smg[r * 72 + cl];
                        *(__half2*)&hu[(size_t)(row0 + r) * FFD + p64 + cl] =
                            __floats2half2_rn(v0 * g.x, v1 * g.y);
                    }
                }
        }
        return;
    }

#pragma unroll
    for (int mt = 0; mt < 4; mt++) {
#pragma unroll
        for (int nt = 0; nt < 4; nt++) {
            int row = row0 + wr*64 + mt*16 + rp;
            int col = col0 + wc*32 + nt*8 + 2*cp;
#pragma unroll
            for (int half_ = 0; half_ < 2; half_++) {
                int r = row + half_ * 8;
                float v0 = acc[mt][nt][half_*2 + 0] + bias[col];
                float v1 = acc[mt][nt][half_*2 + 1] + bias[col + 1];
                if (EPI == 5) {
                    if (col < 1088) {            // q or k: fused RoPE rotation
                        int jj = (col & 63) >> 1;
                        float2 cs = __ldg(&rope[(r & (SS-1)) * 32 + jj]);
                        float o0 = v0 * cs.x - v1 * cs.y;
                        float o1 = v0 * cs.y + v1 * cs.x;
                        if (col < 1024) { o0 *= 0.125f; o1 *= 0.125f; }
                        v0 = o0; v1 = o1;
                    }
                    __half2 o = __floats2half2_rn(v0, v1);
                    if (col < 1024)
                        *(__half2*)((__half*)Cv + (size_t)r * N + col) = o;
                    else
                        *(__half2*)((__half*)extra + (size_t)r * 128 + (col - 1024)) = o;
                } else { // EPI 1
                    size_t gi = (size_t)r * N + col;
                    float2 e = *(const float2*)((const float*)extra + gi);
                    *(float2*)((float*)Cv + gi) = make_float2(v0 + e.x, v1 + e.y);
                }
            }
        }
    }
}

// ---------------- fused weight prep: transposes + rope table + permuted q/k ----------
// tile ranges: wq[0,256) wk[256,272) wv[272,288) wo[288,544) wg[544,1568)
//              wu[1568,2592) wd[2592,3616)
// wq/wk columns permuted within each 64-head: slot 2j <- col j, slot 2j+1 <- col j+32
#define WPREP_BLOCKS 3616
__global__ void __launch_bounds__(256)
wprep_kernel(const float* __restrict__ wq, const float* __restrict__ wk,
             const float* __restrict__ wv, const float* __restrict__ wo,
             const float* __restrict__ wg, const float* __restrict__ wu,
             const float* __restrict__ wd,
             __half* __restrict__ wqkvT, __half* __restrict__ woT,
             __half* __restrict__ wguT, __half* __restrict__ wdT,
             const float* __restrict__ bq, const float* __restrict__ bk,
             const float* __restrict__ bv, const float* __restrict__ bg,
             const float* __restrict__ bu,
             float* __restrict__ bqkv, float* __restrict__ bgu,
             float2* __restrict__ ropetab) {
    const int bidx = blockIdx.x;
    const int tid = threadIdx.x;

    if (bidx == 0) {   // bias concat with q/k head-dim permutation
#pragma unroll
        for (int j = 0; j < 5; j++) {
            int i = tid + j * 256;
            if (i < 1152) {
                if (i < 1024) {
                    int slot = i & 63;
                    int orig = (slot & 1) ? (slot >> 1) + 32 : (slot >> 1);
                    bqkv[i] = bq[(i & ~63) | orig];
                } else if (i < 1088) {
                    int slot = i - 1024;
                    int orig = (slot & 1) ? (slot >> 1) + 32 : (slot >> 1);
                    bqkv[i] = bk[orig];
                } else {
                    bqkv[i] = bv[i - 1088];
                }
            }
        }
    }
    if (bidx == 1) {
#pragma unroll
        for (int j = 0; j < 32; j++) {
            int i = tid + j * 256;
            int p = i >> 7, r = i & 127;
            bgu[i] = (r < 64) ? bg[p*64 + r] : bu[p*64 + (r - 64)];
        }
    }
    if (bidx >= 2 && bidx < 258) {          // rope table: 256 entries per block
        int e = (bidx - 2) * 256 + tid;
        int s = e >> 5, j = e & 31;
        float inv = exp2f((float)j * -0.41524101186092029f);   // -log2(10000)/32
        float c, sn;
        sincosf((float)s * inv, &sn, &c);
        ropetab[e] = make_float2(c, sn);
    }

    const float* W; __half* WT; int K, N, t, nbase;
    bool qkperm = false;
    if      (bidx < 256)  { W = wq; WT = wqkvT;           K = EE;  N = EE;  t = bidx;        qkperm = true; }
    else if (bidx < 272)  { W = wk; WT = wqkvT + 1024*EE; K = EE;  N = 64;  t = bidx - 256;  qkperm = true; }
    else if (bidx < 288)  { W = wv; WT = wqkvT + 1088*EE; K = EE;  N = 64;  t = bidx - 272;  }
    else if (bidx < 544)  { W = wo; WT = woT;             K = EE;  N = EE;  t = bidx - 288;  }
    else if (bidx < 1568) { W = wg; WT = wguT;            K = EE;  N = FFD; t = bidx - 544;  }
    else if (bidx < 2592) { W = wu; WT = wguT;            K = EE;  N = FFD; t = bidx - 1568; }
    else                  { W = wd; WT = wdT;             K = FFD; N = EE;  t = bidx - 2592; }

    const int tilesX = N >> 6;
    const int nb = (t % tilesX) * 64, kb = (t / tilesX) * 64;
    if (bidx >= 544 && bidx < 1568)       nbase = (nb >> 6) * 128;        // gate half
    else if (bidx >= 1568 && bidx < 2592) nbase = (nb >> 6) * 128 + 64;   // up half
    else                                   nbase = nb;

    __shared__ float sm[64][65];
    const int x = tid & 15, y = tid >> 4;
#pragma unroll
    for (int j = 0; j < 4; j++) {
        int r = y + j * 16;
        float4 v = *(const float4*)&W[(size_t)(kb + r) * N + nb + x * 4];
        sm[x*4 + 0][r] = v.x; sm[x*4 + 1][r] = v.y;
        sm[x*4 + 2][r] = v.z; sm[x*4 + 3][r] = v.w;
    }
    __syncthreads();
    const int lane = tid & 31, w = tid >> 5;
#pragma unroll
    for (int j = 0; j < 8; j++) {
        int n = w * 8 + j;
        int ndst = qkperm ? (((n & 31) << 1) | (n >> 5)) : n;   // head-dim perm
        __half2 h2 = __floats2half2_rn(sm[n][lane*2], sm[n][lane*2 + 1]);
        *(uint32_t*)&WT[(size_t)(nbase + ndst) * K + kb + lane*2] = *(uint32_t*)&h2;
    }
}

// ---------------- rmsnorm (fp16 output) ----------------
__global__ void rmsnorm_kernel(const float* __restrict__ x, const float* __restrict__ g,
                               __half* __restrict__ out) {
    int row = blockIdx.x;
    const float* xr = x + (size_t)row * EE;
    float v[4];
    float s = 0.f;
#pragma unroll
    for (int i = 0; i < 4; i++) { v[i] = xr[threadIdx.x + i*256]; s += v[i]*v[i]; }
    __shared__ float red[8];
#pragma unroll
    for (int o = 16; o > 0; o >>= 1) s += __shfl_xor_sync(0xffffffffu, s, o);
    if ((threadIdx.x & 31) == 0) red[threadIdx.x >> 5] = s;
    __syncthreads();
    if (threadIdx.x < 8) {
        float t = red[threadIdx.x];
#pragma unroll
        for (int o = 4; o > 0; o >>= 1) t += __shfl_xor_sync(0xffu, t, o);
        if (threadIdx.x == 0) red[0] = t;
    }
    __syncthreads();
    float ms = red[0] * (1.0f / EE);
    float r  = rsqrtf(ms + 1.1920929e-7f);
#pragma unroll
    for (int i = 0; i < 4; i++) {
        int c = threadIdx.x + i*256;
        out[(size_t)row*EE + c] = __float2half_rn(v[i] * r * g[c]);
    }
}

// ---------------- Flash attention, fp16 m16n8k16 (MQA, causal, HD=64) ----------------
// q/k head-dim permuted consistently (QK^T invariant); v original layout.
#define ATT_SMEM 46080
__global__ void __launch_bounds__(128)
attn_mma(const __half* __restrict__ q, const __half* __restrict__ kv,
         __half* __restrict__ out) {
    extern __shared__ char smc[];
    const uint32_t sb = smem_u32(smc);
    const int tid = threadIdx.x, lane = tid & 31, w = tid >> 5;
    const int bh = blockIdx.y, b = bh >> 4, h = bh & 15;
    const int qb = (int)(gridDim.x - 1 - blockIdx.x);
    const int rp = lane >> 2, cp = lane & 3;

    const uint32_t qs = sb;
    const uint32_t a_lm = (uint32_t)((w*16 + (lane & 15)) * 144 + ((lane >> 4) & 1) * 16);
    const uint32_t b_lm = (uint32_t)(((lane & 7) + ((lane >> 4) & 1) * 8) * 144
                                     + ((lane >> 3) & 1) * 16);
    const uint32_t v_lm = (uint32_t)(((lane & 7) + ((lane >> 3) & 1) * 8) * 144
                                     + ((lane >> 4) & 1) * 16);

    const __half* qg = q + ((size_t)(b*SS + qb*64)) * 1024 + h*64;
#pragma unroll
    for (int i = 0; i < 4; i++) {
        int f = tid + i * 128;
        int r = f >> 3, c = f & 7;
        cpasync16(qs + (uint32_t)(r * 144 + c * 16), qg + (size_t)r * 1024 + c * 8);
    }
    const __half* kg = kv + (size_t)(b*SS) * 128;
    const __half* vg = kg + 64;
    auto issue_kv = [&](int buf, int kb) {
        uint32_t ksm = sb + 9216u + (uint32_t)buf * 18432u;
        uint32_t vsm = ksm + 9216u;
#pragma unroll
        for (int i = 0; i < 4; i++) {
            int f = tid + i * 128;
            int r = f >> 3, c = f & 7;
            size_t gof = (size_t)(kb*64 + r) * 128 + c * 8;
            cpasync16(ksm + (uint32_t)(r * 144 + c * 16), kg + gof);
            cpasync16(vsm + (uint32_t)(r * 144 + c * 16), vg + gof);
        }
        asm volatile("cp.async.commit_group;" ::: "memory");
    };
    issue_kv(0, 0);

    float o[8][4];
#pragma unroll
    for (int nt = 0; nt < 8; nt++)
#pragma unroll
        for (int j = 0; j < 4; j++) o[nt][j] = 0.f;
    float m0 = -1e30f, m1 = -1e30f, l0 = 0.f, l1 = 0.f;

    for (int kb = 0; kb <= qb; kb++) {
        int buf = kb & 1;
        if (kb < qb) {
            issue_kv(buf ^ 1, kb + 1);
            asm volatile("cp.async.wait_group 1;" ::: "memory");
        } else {
            asm volatile("cp.async.wait_group 0;" ::: "memory");
        }
        __syncthreads();
        const uint32_t ksm = sb + 9216u + (uint32_t)buf * 18432u;
        const uint32_t vsm = ksm + 9216u;

        float s[8][4];
#pragma unroll
        for (int nt = 0; nt < 8; nt++)
#pragma unroll
            for (int j = 0; j < 4; j++) s[nt][j] = 0.f;
#pragma unroll
        for (int ks = 0; ks < 4; ks++) {
            uint32_t af[4];
            ldsm4(qs + a_lm + (uint32_t)(ks * 32), af[0], af[1], af[2], af[3]);
#pragma unroll
            for (int p2 = 0; p2 < 4; p2++) {
                uint32_t bf[4];
                ldsm4(ksm + b_lm + (uint32_t)(p2 * 16 * 144 + ks * 32),
                      bf[0], bf[1], bf[2], bf[3]);
                mma_f16(s[p2*2],     af, &bf[0]);
                mma_f16(s[p2*2 + 1], af, &bf[2]);
            }
        }

        if (kb == qb) {
#pragma unroll
            for (int nt = 0; nt < 8; nt++) {
                int key0 = nt*8 + 2*cp;
                int r0 = w*16 + rp, r1 = r0 + 8;
                if (key0     > r0) s[nt][0] = -1e30f;
                if (key0 + 1 > r0) s[nt][1] = -1e30f;
                if (key0     > r1) s[nt][2] = -1e30f;
                if (key0 + 1 > r1) s[nt][3] = -1e30f;
            }
        }

        float mx0 = -1e30f, mx1 = -1e30f;
#pragma unroll
        for (int nt = 0; nt < 8; nt++) {
            mx0 = fmaxf(mx0, fmaxf(s[nt][0], s[nt][1]));
            mx1 = fmaxf(mx1, fmaxf(s[nt][2], s[nt][3]));
        }
        mx0 = fmaxf(mx0, __shfl_xor_sync(0xffffffffu, mx0, 1, 4));
        mx0 = fmaxf(mx0, __shfl_xor_sync(0xffffffffu, mx0, 2, 4));
        mx1 = fmaxf(mx1, __shfl_xor_sync(0xffffffffu, mx1, 1, 4));
        mx1 = fmaxf(mx1, __shfl_xor_sync(0xffffffffu, mx1, 2, 4));
        float mn0 = fmaxf(m0, mx0), mn1 = fmaxf(m1, mx1);
        float al0 = __expf(m0 - mn0), al1 = __expf(m1 - mn1);
        float sum0 = 0.f, sum1 = 0.f;
        uint32_t ph[8][2];
#pragma unroll
        for (int nt = 0; nt < 8; nt++) {
            float e0 = __expf(s[nt][0] - mn0);
            float e1 = __expf(s[nt][1] - mn0);
            float e2 = __expf(s[nt][2] - mn1);
            float e3 = __expf(s[nt][3] - mn1);
            sum0 += e0 + e1; sum1 += e2 + e3;
            ph[nt][0] = packh2(e0, e1);
            ph[nt][1] = packh2(e2, e3);
        }
        sum0 += __shfl_xor_sync(0xffffffffu, sum0, 1, 4);
        sum0 += __shfl_xor_sync(0xffffffffu, sum0, 2, 4);
        sum1 += __shfl_xor_sync(0xffffffffu, sum1, 1, 4);
        sum1 += __shfl_xor_sync(0xffffffffu, sum1, 2, 4);
        l0 = l0 * al0 + sum0; l1 = l1 * al1 + sum1;
        m0 = mn0; m1 = mn1;
#pragma unroll
        for (int nt = 0; nt < 8; nt++) {
            o[nt][0] *= al0; o[nt][1] *= al0;
            o[nt][2] *= al1; o[nt][3] *= al1;
        }

#pragma unroll
        for (int kt = 0; kt < 4; kt++) {
            uint32_t pa[4] = { ph[2*kt][0], ph[2*kt][1], ph[2*kt+1][0], ph[2*kt+1][1] };
#pragma unroll
            for (int np = 0; np < 4; np++) {
                uint32_t bf[4];
                ldsm4t(vsm + v_lm + (uint32_t)(kt * 16 * 144 + np * 32),
                       bf[0], bf[1], bf[2], bf[3]);
                mma_f16(o[np*2],     pa, &bf[0]);
                mma_f16(o[np*2 + 1], pa, &bf[2]);
            }
        }
        __syncthreads();
    }

    float inv0 = 1.0f / l0, inv1 = 1.0f / l1;
    const int r0 = b*SS + qb*64 + w*16 + rp;
#pragma unroll
    for (int nt = 0; nt < 8; nt++) {
        int d = h*64 + nt*8 + 2*cp;
        *(__half2*)&out[(size_t)r0 * 1024 + d] =
            __floats2half2_rn(o[nt][0] * inv0, o[nt][1] * inv0);
        *(__half2*)&out[(size_t)(r0 + 8) * 1024 + d] =
            __floats2half2_rn(o[nt][2] * inv1, o[nt][3] * inv1);
    }
}

// ---------------- launch ----------------
extern "C" void kernel_launch(void* const* d_in, const int* in_sizes, int n_in,
                              void* d_out, int out_size) {
    const float* x  = (const float*)d_in[0];
    const float* wq = (const float*)d_in[1];
    const float* bq = (const float*)d_in[2];
    const float* wk = (const float*)d_in[3];
    const float* bk = (const float*)d_in[4];
    const float* wv = (const float*)d_in[5];
    const float* bv = (const float*)d_in[6];
    const float* wo = (const float*)d_in[7];
    const float* bo = (const float*)d_in[8];
    const float* wg = (const float*)d_in[9];
    const float* bg = (const float*)d_in[10];
    const float* wu = (const float*)d_in[11];
    const float* bu = (const float*)d_in[12];
    const float* wd = (const float*)d_in[13];
    const float* bd = (const float*)d_in[14];
    const float* g1 = (const float*)d_in[15];
    const float* g2 = (const float*)d_in[16];
    float* out = (float*)d_out;

    __half *h, *qb_, *kv, *att, *hu;
    __half *wqkvT, *woT, *wguT, *wdT;
    float *x1, *bqkv, *bgu;
    float2* ropetab;
    cudaGetSymbolAddress((void**)&h,       g_h);
    cudaGetSymbolAddress((void**)&qb_,     g_q);
    cudaGetSymbolAddress((void**)&kv,      g_kv);
    cudaGetSymbolAddress((void**)&att,     g_att);
    cudaGetSymbolAddress((void**)&x1,      g_x1);
    cudaGetSymbolAddress((void**)&hu,      g_hu);
    cudaGetSymbolAddress((void**)&wqkvT,   g_wqkvT);
    cudaGetSymbolAddress((void**)&woT,     g_woT);
    cudaGetSymbolAddress((void**)&wguT,    g_wguT);
    cudaGetSymbolAddress((void**)&wdT,     g_wdT);
    cudaGetSymbolAddress((void**)&bqkv,    g_bqkv);
    cudaGetSymbolAddress((void**)&bgu,     g_bgu);
    cudaGetSymbolAddress((void**)&ropetab, g_ropetab);

    cudaFuncSetAttribute(mma_gemm<1>, cudaFuncAttributeMaxDynamicSharedMemorySize, GEMM_SMEM);
    cudaFuncSetAttribute(mma_gemm<5>, cudaFuncAttributeMaxDynamicSharedMemorySize, GEMM_SMEM);
    cudaFuncSetAttribute(mma_gemm<6>, cudaFuncAttributeMaxDynamicSharedMemorySize, GEMM_SMEM);
    cudaFuncSetAttribute(attn_mma,    cudaFuncAttributeMaxDynamicSharedMemorySize, ATT_SMEM);

    // 0) fused weight prep (transposes + permuted q/k + biases + rope table)
    wprep_kernel<<<WPREP_BLOCKS, 256>>>(wq, wk, wv, wo, wg, wu, wd,
                                        wqkvT, woT, wguT, wdT,
                                        bq, bk, bv, bg, bu, bqkv, bgu, ropetab);
    // 1) rmsnorm(x, g1) -> h (fp16)
    rmsnorm_kernel<<<MM, 256>>>(x, g1, h);
    // 2) fused QKV projection + RoPE (in-epilogue)
    mma_gemm<5><<<dim3(1152/128, MM/128), 256, GEMM_SMEM>>>(h, wqkvT, bqkv, kv, qb_, EE, EE, ropetab);
    // 3) attention (64-row Q tiles)
    attn_mma<<<dim3(SS/64, BB*HH), 128, ATT_SMEM>>>(qb_, kv, att);
    // 4) o-proj + residual(x) -> x1 (fp32)
    mma_gemm<1><<<dim3(EE/128, MM/128), 256, GEMM_SMEM>>>(att, woT, bo, x, x1, EE, EE, nullptr);
    // 5) rmsnorm(x1, g2) -> h (fp16)
    rmsnorm_kernel<<<MM, 256>>>(x1, g2, h);
    // 6) fused FFN: hu = fp16(gelu(h@wg+bg) * (h@wu+bu))
    mma_gemm<6><<<dim3(2*FFD/128, MM/128), 256, GEMM_SMEM>>>(h, wguT, bgu, nullptr, hu, 2*FFD, EE, nullptr);
    // 7) out = hu@wd + bd + x1 (fp32)
    mma_gemm<1><<<dim3(EE/128, MM/128), 256, GEMM_SMEM>>>(hu, wdT, bd, x1, out, EE, FFD, nullptr);
}

// round 15
// speedup vs baseline: 1.0021x; 1.0009x over previous
#include <cuda_runtime.h>
#include <cuda_fp16.h>
#include <stdint.h>
#include <math.h>

#define BB  2
#define SS  2048
#define EE  1024
#define HH  16
#define HD_ 64
#define FFD 4096
#define MM  (BB*SS)   // 4096

// ---------------- scratch (allocation-free) ----------------
static __device__ __half g_h    [MM*EE];
static __device__ __half g_q    [MM*EE];      // q, RoPE'd, head-dim permuted
static __device__ __half g_kv   [MM*128];     // packed [k(permuted,roped) | v]
static __device__ __half g_att  [MM*EE];
static __device__ float  g_x1   [MM*EE];
static __device__ __half g_hu   [MM*FFD];
// transposed fp16 weights
static __device__ __half g_wqkvT[1152*EE];    // 0-1023 wq(perm), 1024-1087 wk(perm), 1088-1151 wv
static __device__ __half g_woT  [EE*EE];
static __device__ __half g_wguT [2*FFD*EE];   // interleaved: block p = [64 wg | 64 wu]
static __device__ __half g_wdT  [EE*FFD];
static __device__ float  g_bqkv [1152];       // permuted q/k bias
static __device__ float  g_bgu  [2*FFD];
static __device__ float2 g_ropetab[SS*32];    // (cos, sin) per (s, j)

// =================== helpers ===================
__device__ __forceinline__ uint32_t smem_u32(const void* p) {
    uint32_t a;
    asm("{ .reg .u64 t; cvta.to.shared.u64 t, %1; cvt.u32.u64 %0, t; }"
        : "=r"(a) : "l"(p));
    return a;
}
__device__ __forceinline__ void cpasync16(uint32_t sp, const void* gp) {
    asm volatile("cp.async.ca.shared.global [%0], [%1], 16;" :: "r"(sp), "l"(gp) : "memory");
}
__device__ __forceinline__ void ldsm4(uint32_t addr, uint32_t& r0, uint32_t& r1,
                                      uint32_t& r2, uint32_t& r3) {
    asm volatile("ldmatrix.sync.aligned.m8n8.x4.shared.b16 {%0,%1,%2,%3}, [%4];"
                 : "=r"(r0), "=r"(r1), "=r"(r2), "=r"(r3) : "r"(addr));
}
__device__ __forceinline__ void ldsm4t(uint32_t addr, uint32_t& r0, uint32_t& r1,
                                       uint32_t& r2, uint32_t& r3) {
    asm volatile("ldmatrix.sync.aligned.m8n8.x4.trans.shared.b16 {%0,%1,%2,%3}, [%4];"
                 : "=r"(r0), "=r"(r1), "=r"(r2), "=r"(r3) : "r"(addr));
}
__device__ __forceinline__ void mma_f16(float* d, const uint32_t* a, const uint32_t* b) {
    asm volatile(
        "mma.sync.aligned.m16n8k16.row.col.f32.f16.f16.f32 "
        "{%0,%1,%2,%3}, {%4,%5,%6,%7}, {%8,%9}, {%0,%1,%2,%3};"
        : "+f"(d[0]), "+f"(d[1]), "+f"(d[2]), "+f"(d[3])
        : "r"(a[0]), "r"(a[1]), "r"(a[2]), "r"(a[3]), "r"(b[0]), "r"(b[1]));
}
__device__ __forceinline__ uint32_t packh2(float a, float b) {
    __half2 h = __floats2half2_rn(a, b);
    return *(uint32_t*)&h;
}

// GEMM smem: per stage {A[128][40] + B[128][40]} halves (pitch 80 B); 3 stages
#define OP_BYTES   10240
#define STAGE_B    (2 * OP_BYTES)     // 20480
#define GEMM_SMEM  (3 * STAGE_B)      // 61440

// =================== fp16 mma.sync GEMM (3-stage, K-chunk 32, 1 sync/chunk) ===========
// C = A[M,K] @ WT[N,K]^T + bias. EPI: 1=+bias+extra(f32)->f32;
// 5=QKV split + fused RoPE; 6=fused gelu-gate*up -> hu
template<int EPI>
__global__ void __launch_bounds__(256, 2)
mma_gemm(const __half* __restrict__ A, const __half* __restrict__ WT,
         const float* __restrict__ bias, const void* extra,
         void* __restrict__ Cv, int N, int K, const float2* __restrict__ rope) {
    extern __shared__ char dyn[];
    const uint32_t smem_base = smem_u32(dyn);

    const int tid  = threadIdx.x;
    const int lane = tid & 31;
    const int warp = tid >> 5;
    const int wr = warp & 1;
    const int wc = warp >> 1;
    const int row0 = blockIdx.y * 128, col0 = blockIdx.x * 128;
    const int rp = lane >> 2;
    const int cp = lane & 3;

    const uint32_t a_lm = (uint32_t)((wr*64 + (lane & 15)) * 80 + ((lane >> 4) & 1) * 16);
    const uint32_t b_lm = (uint32_t)((wc*32 + (lane & 7) + ((lane >> 4) & 1) * 8) * 80
                                     + ((lane >> 3) & 1) * 16);

    float acc[4][4][4];
#pragma unroll
    for (int i = 0; i < 4; i++)
#pragma unroll
        for (int j = 0; j < 4; j++)
#pragma unroll
            for (int q = 0; q < 4; q++) acc[i][j][q] = 0.f;

    auto issue = [&](int buf, int kb) {
        uint32_t as = smem_base + (uint32_t)buf * STAGE_B;
        uint32_t bs = as + OP_BYTES;
#pragma unroll
        for (int i = 0; i < 2; i++) {
            int f = tid + i * 256;
            int r = f >> 2, c = f & 3;
            cpasync16(as + (uint32_t)(r * 80 + c * 16),
                      A + (size_t)(row0 + r) * K + kb + c * 8);
        }
#pragma unroll
        for (int i = 0; i < 2; i++) {
            int f = tid + i * 256;
            int r = f >> 2, c = f & 3;
            cpasync16(bs + (uint32_t)(r * 80 + c * 16),
                      WT + (size_t)(col0 + r) * K + kb + c * 8);
        }
        asm volatile("cp.async.commit_group;" ::: "memory");
    };

    auto compute = [&](int buf) {
        const uint32_t as = smem_base + (uint32_t)buf * STAGE_B + a_lm;
        const uint32_t bs = smem_base + (uint32_t)buf * STAGE_B + OP_BYTES + b_lm;
#pragma unroll
        for (int ks = 0; ks < 2; ks++) {
            uint32_t af[4][4];
#pragma unroll
            for (int mt = 0; mt < 4; mt++)
                ldsm4(as + (uint32_t)(mt * 1280 + ks * 32),
                      af[mt][0], af[mt][1], af[mt][2], af[mt][3]);
            uint32_t bf[4][2];
            ldsm4(bs + (uint32_t)(ks * 32),        bf[0][0], bf[0][1], bf[1][0], bf[1][1]);
            ldsm4(bs + (uint32_t)(1280 + ks * 32), bf[2][0], bf[2][1], bf[3][0], bf[3][1]);
#pragma unroll
            for (int mt = 0; mt < 4; mt++)
#pragma unroll
                for (int nt = 0; nt < 4; nt++)
                    mma_f16(acc[mt][nt], af[mt], bf[nt]);
        }
    };

    const int nk = K >> 5;
    issue(0, 0); issue(1, 32);
    int cur = 0, nxt = 2;
    for (int kt = 0; kt < nk; kt++) {
        if (kt == nk - 1) asm volatile("cp.async.wait_group 0;" ::: "memory");
        else              asm volatile("cp.async.wait_group 1;" ::: "memory");
        __syncthreads();
        if (kt + 2 < nk) { issue(nxt, (kt + 2) << 5); nxt = (nxt == 2) ? 0 : nxt + 1; }
        compute(cur);
        cur = (cur == 2) ? 0 : cur + 1;
    }

    // ---------------- epilogue ----------------
    if (EPI == 6) {
        float* smg = (float*)dyn;                // 128 x 72 fp32
        __syncthreads();
        if (wc < 2) {
#pragma unroll
            for (int mt = 0; mt < 4; mt++)
#pragma unroll
                for (int nt = 0; nt < 4; nt++) {
                    int rl = wr*64 + mt*16 + rp;
                    int cl = wc*32 + nt*8 + 2*cp;
#pragma unroll
                    for (int half_ = 0; half_ < 2; half_++) {
                        int r = rl + half_ * 8;
                        float v0 = acc[mt][nt][half_*2 + 0] + bias[col0 + cl];
                        float v1 = acc[mt][nt][half_*2 + 1] + bias[col0 + cl + 1];
                        v0 = 0.5f * v0 * (1.0f + erff(v0 * 0.7071067811865476f));
                        v1 = 0.5f * v1 * (1.0f + erff(v1 * 0.7071067811865476f));
                        *(float2*)&smg[r * 72 + cl] = make_float2(v0, v1);
                    }
                }
        }
        __syncthreads();
        if (wc >= 2) {
            __half* hu = (__half*)Cv;
            const int p64 = (col0 >> 7) * 64;
#pragma unroll
            for (int mt = 0; mt < 4; mt++)
#pragma unroll
                for (int nt = 0; nt < 4; nt++) {
                    int rl = wr*64 + mt*16 + rp;
                    int cl = (wc - 2)*32 + nt*8 + 2*cp;
#pragma unroll
                    for (int half_ = 0; half_ < 2; half_++) {
                        int r = rl + half_ * 8;
                        float v0 = acc[mt][nt][half_*2 + 0] + bias[col0 + 64 + cl];
                        float v1 = acc[mt][nt][half_*2 + 1] + bias[col0 + 64 + cl + 1];
                        float2 g = *(const float2*)&smg[r * 72 + cl];
                        *(__half2*)&hu[(size_t)(row0 + r) * FFD + p64 + cl] =
                            __floats2half2_rn(v0 * g.x, v1 * g.y);
                    }
                }
        }
        return;
    }

#pragma unroll
    for (int mt = 0; mt < 4; mt++) {
#pragma unroll
        for (int nt = 0; nt < 4; nt++) {
            int row = row0 + wr*64 + mt*16 + rp;
            int col = col0 + wc*32 + nt*8 + 2*cp;
#pragma unroll
            for (int half_ = 0; half_ < 2; half_++) {
                int r = row + half_ * 8;
                float v0 = acc[mt][nt][half_*2 + 0] + bias[col];
                float v1 = acc[mt][nt][half_*2 + 1] + bias[col + 1];
                if (EPI == 5) {
                    if (col < 1088) {            // q or k: fused RoPE rotation
                        int jj = (col & 63) >> 1;
                        float2 cs = __ldg(&rope[(r & (SS-1)) * 32 + jj]);
                        float o0 = v0 * cs.x - v1 * cs.y;
                        float o1 = v0 * cs.y + v1 * cs.x;
                        if (col < 1024) { o0 *= 0.125f; o1 *= 0.125f; }
                        v0 = o0; v1 = o1;
                    }
                    __half2 o = __floats2half2_rn(v0, v1);
                    if (col < 1024)
                        *(__half2*)((__half*)Cv + (size_t)r * N + col) = o;
                    else
                        *(__half2*)((__half*)extra + (size_t)r * 128 + (col - 1024)) = o;
                } else { // EPI 1
                    size_t gi = (size_t)r * N + col;
                    float2 e = *(const float2*)((const float*)extra + gi);
                    *(float2*)((float*)Cv + gi) = make_float2(v0 + e.x, v1 + e.y);
                }
            }
        }
    }
}

// ---------------- fused weight prep: transposes + rope table + permuted q/k ----------
#define WPREP_BLOCKS 3616
__global__ void __launch_bounds__(256)
wprep_kernel(const float* __restrict__ wq, const float* __restrict__ wk,
             const float* __restrict__ wv, const float* __restrict__ wo,
             const float* __restrict__ wg, const float* __restrict__ wu,
             const float* __restrict__ wd,
             __half* __restrict__ wqkvT, __half* __restrict__ woT,
             __half* __restrict__ wguT, __half* __restrict__ wdT,
             const float* __restrict__ bq, const float* __restrict__ bk,
             const float* __restrict__ bv, const float* __restrict__ bg,
             const float* __restrict__ bu,
             float* __restrict__ bqkv, float* __restrict__ bgu,
             float2* __restrict__ ropetab) {
    const int bidx = blockIdx.x;
    const int tid = threadIdx.x;

    if (bidx == 0) {   // bias concat with q/k head-dim permutation
#pragma unroll
        for (int j = 0; j < 5; j++) {
            int i = tid + j * 256;
            if (i < 1152) {
                if (i < 1024) {
                    int slot = i & 63;
                    int orig = (slot & 1) ? (slot >> 1) + 32 : (slot >> 1);
                    bqkv[i] = bq[(i & ~63) | orig];
                } else if (i < 1088) {
                    int slot = i - 1024;
                    int orig = (slot & 1) ? (slot >> 1) + 32 : (slot >> 1);
                    bqkv[i] = bk[orig];
                } else {
                    bqkv[i] = bv[i - 1088];
                }
            }
        }
    }
    if (bidx == 1) {
#pragma unroll
        for (int j = 0; j < 32; j++) {
            int i = tid + j * 256;
            int p = i >> 7, r = i & 127;
            bgu[i] = (r < 64) ? bg[p*64 + r] : bu[p*64 + (r - 64)];
        }
    }
    if (bidx >= 2 && bidx < 258) {
        int e = (bidx - 2) * 256 + tid;
        int s = e >> 5, j = e & 31;
        float inv = exp2f((float)j * -0.41524101186092029f);
        float c, sn;
        sincosf((float)s * inv, &sn, &c);
        ropetab[e] = make_float2(c, sn);
    }

    const float* W; __half* WT; int K, N, t, nbase;
    bool qkperm = false;
    if      (bidx < 256)  { W = wq; WT = wqkvT;           K = EE;  N = EE;  t = bidx;        qkperm = true; }
    else if (bidx < 272)  { W = wk; WT = wqkvT + 1024*EE; K = EE;  N = 64;  t = bidx - 256;  qkperm = true; }
    else if (bidx < 288)  { W = wv; WT = wqkvT + 1088*EE; K = EE;  N = 64;  t = bidx - 272;  }
    else if (bidx < 544)  { W = wo; WT = woT;             K = EE;  N = EE;  t = bidx - 288;  }
    else if (bidx < 1568) { W = wg; WT = wguT;            K = EE;  N = FFD; t = bidx - 544;  }
    else if (bidx < 2592) { W = wu; WT = wguT;            K = EE;  N = FFD; t = bidx - 1568; }
    else                  { W = wd; WT = wdT;             K = FFD; N = EE;  t = bidx - 2592; }

    const int tilesX = N >> 6;
    const int nb = (t % tilesX) * 64, kb = (t / tilesX) * 64;
    if (bidx >= 544 && bidx < 1568)       nbase = (nb >> 6) * 128;
    else if (bidx >= 1568 && bidx < 2592) nbase = (nb >> 6) * 128 + 64;
    else                                   nbase = nb;

    __shared__ float sm[64][65];
    const int x = tid & 15, y = tid >> 4;
#pragma unroll
    for (int j = 0; j < 4; j++) {
        int r = y + j * 16;
        float4 v = *(const float4*)&W[(size_t)(kb + r) * N + nb + x * 4];
        sm[x*4 + 0][r] = v.x; sm[x*4 + 1][r] = v.y;
        sm[x*4 + 2][r] = v.z; sm[x*4 + 3][r] = v.w;
    }
    __syncthreads();
    const int lane = tid & 31, w = tid >> 5;
#pragma unroll
    for (int j = 0; j < 8; j++) {
        int n = w * 8 + j;
        int ndst = qkperm ? (((n & 31) << 1) | (n >> 5)) : n;
        __half2 h2 = __floats2half2_rn(sm[n][lane*2], sm[n][lane*2 + 1]);
        *(uint32_t*)&WT[(size_t)(nbase + ndst) * K + kb + lane*2] = *(uint32_t*)&h2;
    }
}

// ---------------- rmsnorm (fp16 output) ----------------
__global__ void rmsnorm_kernel(const float* __restrict__ x, const float* __restrict__ g,
                               __half* __restrict__ out) {
    int row = blockIdx.x;
    const float* xr = x + (size_t)row * EE;
    float v[4];
    float s = 0.f;
#pragma unroll
    for (int i = 0; i < 4; i++) { v[i] = xr[threadIdx.x + i*256]; s += v[i]*v[i]; }
    __shared__ float red[8];
#pragma unroll
    for (int o = 16; o > 0; o >>= 1) s += __shfl_xor_sync(0xffffffffu, s, o);
    if ((threadIdx.x & 31) == 0) red[threadIdx.x >> 5] = s;
    __syncthreads();
    if (threadIdx.x < 8) {
        float t = red[threadIdx.x];
#pragma unroll
        for (int o = 4; o > 0; o >>= 1) t += __shfl_xor_sync(0xffu, t, o);
        if (threadIdx.x == 0) red[0] = t;
    }
    __syncthreads();
    float ms = red[0] * (1.0f / EE);
    float r  = rsqrtf(ms + 1.1920929e-7f);
#pragma unroll
    for (int i = 0; i < 4; i++) {
        int c = threadIdx.x + i*256;
        out[(size_t)row*EE + c] = __float2half_rn(v[i] * r * g[c]);
    }
}

// ---------------- Flash attention: 2 heads per CTA share K/V (MQA) ----------------
// 256 thr / 8 warps: warps 0-3 head h0, warps 4-7 head h0+1; 64-row q tile.
// smem: qs[2][64][144B] @0 (18432); per buf {ks,vs} @18432+buf*18432 (9216 each) = 55296
#define ATT_SMEM 55296
__global__ void __launch_bounds__(256)
attn_mma(const __half* __restrict__ q, const __half* __restrict__ kv,
         __half* __restrict__ out) {
    extern __shared__ char smc[];
    const uint32_t sb = smem_u32(smc);
    const int tid = threadIdx.x, lane = tid & 31, w = tid >> 5;
    const int hh = w >> 2, wq_ = w & 3;
    const int b = (int)(blockIdx.y >> 3), h0 = ((int)blockIdx.y & 7) * 2;
    const int qb = (int)(gridDim.x - 1 - blockIdx.x);
    const int rp = lane >> 2, cp = lane & 3;

    const uint32_t qs = sb + (uint32_t)hh * 9216u;
    const uint32_t a_lm = (uint32_t)((wq_*16 + (lane & 15)) * 144 + ((lane >> 4) & 1) * 16);
    const uint32_t b_lm = (uint32_t)(((lane & 7) + ((lane >> 4) & 1) * 8) * 144
                                     + ((lane >> 3) & 1) * 16);
    const uint32_t v_lm = (uint32_t)(((lane & 7) + ((lane >> 3) & 1) * 8) * 144
                                     + ((lane >> 4) & 1) * 16);

    // load Q for both heads (1024 float4 over 256 threads)
    const __half* qg = q + ((size_t)(b*SS + qb*64)) * 1024;
#pragma unroll
    for (int i = 0; i < 4; i++) {
        int f = tid + i * 256;
        int hx = f >> 9, rem = f & 511;
        int r = rem >> 3, c = rem & 7;
        cpasync16(sb + (uint32_t)(hx * 9216 + r * 144 + c * 16),
                  qg + (size_t)r * 1024 + (h0 + hx) * 64 + c * 8);
    }
    const __half* kg = kv + (size_t)(b*SS) * 128;
    const __half* vg = kg + 64;
    auto issue_kv = [&](int buf, int kb) {
        uint32_t ksm = sb + 18432u + (uint32_t)buf * 18432u;
        uint32_t vsm = ksm + 9216u;
#pragma unroll
        for (int i = 0; i < 2; i++) {
            int f = tid + i * 256;
            int r = f >> 3, c = f & 7;
            size_t gof = (size_t)(kb*64 + r) * 128 + c * 8;
            cpasync16(ksm + (uint32_t)(r * 144 + c * 16), kg + gof);
            cpasync16(vsm + (uint32_t)(r * 144 + c * 16), vg + gof);
        }
        asm volatile("cp.async.commit_group;" ::: "memory");
    };
    issue_kv(0, 0);

    float o[8][4];
#pragma unroll
    for (int nt = 0; nt < 8; nt++)
#pragma unroll
        for (int j = 0; j < 4; j++) o[nt][j] = 0.f;
    float m0 = -1e30f, m1 = -1e30f, l0 = 0.f, l1 = 0.f;
    uint32_t afh[4][4];                       // persistent Q fragments

    for (int kb = 0; kb <= qb; kb++) {
        int buf = kb & 1;
        if (kb < qb) {
            issue_kv(buf ^ 1, kb + 1);
            asm volatile("cp.async.wait_group 1;" ::: "memory");
        } else {
            asm volatile("cp.async.wait_group 0;" ::: "memory");
        }
        __syncthreads();
        const uint32_t ksm = sb + 18432u + (uint32_t)buf * 18432u;
        const uint32_t vsm = ksm + 9216u;

        if (kb == 0) {                        // hoist Q fragments once
#pragma unroll
            for (int ks = 0; ks < 4; ks++)
                ldsm4(qs + a_lm + (uint32_t)(ks * 32),
                      afh[ks][0], afh[ks][1], afh[ks][2], afh[ks][3]);
        }

        float s[8][4];
#pragma unroll
        for (int nt = 0; nt < 8; nt++)
#pragma unroll
            for (int j = 0; j < 4; j++) s[nt][j] = 0.f;
#pragma unroll
        for (int ks = 0; ks < 4; ks++) {
#pragma unroll
            for (int p2 = 0; p2 < 4; p2++) {
                uint32_t bf[4];
                ldsm4(ksm + b_lm + (uint32_t)(p2 * 16 * 144 + ks * 32),
                      bf[0], bf[1], bf[2], bf[3]);
                mma_f16(s[p2*2],     afh[ks], &bf[0]);
                mma_f16(s[p2*2 + 1], afh[ks], &bf[2]);
            }
        }

        if (kb == qb) {
#pragma unroll
            for (int nt = 0; nt < 8; nt++) {
                int key0 = nt*8 + 2*cp;
                int r0 = wq_*16 + rp, r1 = r0 + 8;
                if (key0     > r0) s[nt][0] = -1e30f;
                if (key0 + 1 > r0) s[nt][1] = -1e30f;
                if (key0     > r1) s[nt][2] = -1e30f;
                if (key0 + 1 > r1) s[nt][3] = -1e30f;
            }
        }

        float mx0 = -1e30f, mx1 = -1e30f;
#pragma unroll
        for (int nt = 0; nt < 8; nt++) {
            mx0 = fmaxf(mx0, fmaxf(s[nt][0], s[nt][1]));
            mx1 = fmaxf(mx1, fmaxf(s[nt][2], s[nt][3]));
        }
        mx0 = fmaxf(mx0, __shfl_xor_sync(0xffffffffu, mx0, 1, 4));
        mx0 = fmaxf(mx0, __shfl_xor_sync(0xffffffffu, mx0, 2, 4));
        mx1 = fmaxf(mx1, __shfl_xor_sync(0xffffffffu, mx1, 1, 4));
        mx1 = fmaxf(mx1, __shfl_xor_sync(0xffffffffu, mx1, 2, 4));
        float mn0 = fmaxf(m0, mx0), mn1 = fmaxf(m1, mx1);
        float al0 = __expf(m0 - mn0), al1 = __expf(m1 - mn1);
        float sum0 = 0.f, sum1 = 0.f;
        uint32_t ph[8][2];
#pragma unroll
        for (int nt = 0; nt < 8; nt++) {
            float e0 = __expf(s[nt][0] - mn0);
            float e1 = __expf(s[nt][1] - mn0);
            float e2 = __expf(s[nt][2] - mn1);
            float e3 = __expf(s[nt][3] - mn1);
            sum0 += e0 + e1; sum1 += e2 + e3;
            ph[nt][0] = packh2(e0, e1);
            ph[nt][1] = packh2(e2, e3);
        }
        sum0 += __shfl_xor_sync(0xffffffffu, sum0, 1, 4);
        sum0 += __shfl_xor_sync(0xffffffffu, sum0, 2, 4);
        sum1 += __shfl_xor_sync(0xffffffffu, sum1, 1, 4);
        sum1 += __shfl_xor_sync(0xffffffffu, sum1, 2, 4);
        l0 = l0 * al0 + sum0; l1 = l1 * al1 + sum1;
        m0 = mn0; m1 = mn1;
#pragma unroll
        for (int nt = 0; nt < 8; nt++) {
            o[nt][0] *= al0; o[nt][1] *= al0;
            o[nt][2] *= al1; o[nt][3] *= al1;
        }

#pragma unroll
        for (int kt = 0; kt < 4; kt++) {
            uint32_t pa[4] = { ph[2*kt][0], ph[2*kt][1], ph[2*kt+1][0], ph[2*kt+1][1] };
#pragma unroll
            for (int np = 0; np < 4; np++) {
                uint32_t bf[4];
                ldsm4t(vsm + v_lm + (uint32_t)(kt * 16 * 144 + np * 32),
                       bf[0], bf[1], bf[2], bf[3]);
                mma_f16(o[np*2],     pa, &bf[0]);
                mma_f16(o[np*2 + 1], pa, &bf[2]);
            }
        }
        __syncthreads();
    }

    float inv0 = 1.0f / l0, inv1 = 1.0f / l1;
    const int r0 = b*SS + qb*64 + wq_*16 + rp;
    const int h = h0 + hh;
#pragma unroll
    for (int nt = 0; nt < 8; nt++) {
        int d = h*64 + nt*8 + 2*cp;
        *(__half2*)&out[(size_t)r0 * 1024 + d] =
            __floats2half2_rn(o[nt][0] * inv0, o[nt][1] * inv0);
        *(__half2*)&out[(size_t)(r0 + 8) * 1024 + d] =
            __floats2half2_rn(o[nt][2] * inv1, o[nt][3] * inv1);
    }
}

// ---------------- launch ----------------
extern "C" void kernel_launch(void* const* d_in, const int* in_sizes, int n_in,
                              void* d_out, int out_size) {
    const float* x  = (const float*)d_in[0];
    const float* wq = (const float*)d_in[1];
    const float* bq = (const float*)d_in[2];
    const float* wk = (const float*)d_in[3];
    const float* bk = (const float*)d_in[4];
    const float* wv = (const float*)d_in[5];
    const float* bv = (const float*)d_in[6];
    const float* wo = (const float*)d_in[7];
    const float* bo = (const float*)d_in[8];
    const float* wg = (const float*)d_in[9];
    const float* bg = (const float*)d_in[10];
    const float* wu = (const float*)d_in[11];
    const float* bu = (const float*)d_in[12];
    const float* wd = (const float*)d_in[13];
    const float* bd = (const float*)d_in[14];
    const float* g1 = (const float*)d_in[15];
    const float* g2 = (const float*)d_in[16];
    float* out = (float*)d_out;

    __half *h, *qb_, *kv, *att, *hu;
    __half *wqkvT, *woT, *wguT, *wdT;
    float *x1, *bqkv, *bgu;
    float2* ropetab;
    cudaGetSymbolAddress((void**)&h,       g_h);
    cudaGetSymbolAddress((void**)&qb_,     g_q);
    cudaGetSymbolAddress((void**)&kv,      g_kv);
    cudaGetSymbolAddress((void**)&att,     g_att);
    cudaGetSymbolAddress((void**)&x1,      g_x1);
    cudaGetSymbolAddress((void**)&hu,      g_hu);
    cudaGetSymbolAddress((void**)&wqkvT,   g_wqkvT);
    cudaGetSymbolAddress((void**)&woT,     g_woT);
    cudaGetSymbolAddress((void**)&wguT,    g_wguT);
    cudaGetSymbolAddress((void**)&wdT,     g_wdT);
    cudaGetSymbolAddress((void**)&bqkv,    g_bqkv);
    cudaGetSymbolAddress((void**)&bgu,     g_bgu);
    cudaGetSymbolAddress((void**)&ropetab, g_ropetab);

    cudaFuncSetAttribute(mma_gemm<1>, cudaFuncAttributeMaxDynamicSharedMemorySize, GEMM_SMEM);
    cudaFuncSetAttribute(mma_gemm<5>, cudaFuncAttributeMaxDynamicSharedMemorySize, GEMM_SMEM);
    cudaFuncSetAttribute(mma_gemm<6>, cudaFuncAttributeMaxDynamicSharedMemorySize, GEMM_SMEM);
    cudaFuncSetAttribute(attn_mma,    cudaFuncAttributeMaxDynamicSharedMemorySize, ATT_SMEM);

    // 0) fused weight prep (transposes + permuted q/k + biases + rope table)
    wprep_kernel<<<WPREP_BLOCKS, 256>>>(wq, wk, wv, wo, wg, wu, wd,
                                        wqkvT, woT, wguT, wdT,
                                        bq, bk, bv, bg, bu, bqkv, bgu, ropetab);
    // 1) rmsnorm(x, g1) -> h (fp16)
    rmsnorm_kernel<<<MM, 256>>>(x, g1, h);
    // 2) fused QKV projection + RoPE (in-epilogue)
    mma_gemm<5><<<dim3(1152/128, MM/128), 256, GEMM_SMEM>>>(h, wqkvT, bqkv, kv, qb_, EE, EE, ropetab);
    // 3) attention (64-row Q tiles, 2 heads/CTA sharing K/V)
    attn_mma<<<dim3(SS/64, BB*HH/2), 256, ATT_SMEM>>>(qb_, kv, att);
    // 4) o-proj + residual(x) -> x1 (fp32)
    mma_gemm<1><<<dim3(EE/128, MM/128), 256, GEMM_SMEM>>>(att, woT, bo, x, x1, EE, EE, nullptr);
    // 5) rmsnorm(x1, g2) -> h (fp16)
    rmsnorm_kernel<<<MM, 256>>>(x1, g2, h);
    // 6) fused FFN: hu = fp16(gelu(h@wg+bg) * (h@wu+bu))
    mma_gemm<6><<<dim3(2*FFD/128, MM/128), 256, GEMM_SMEM>>>(h, wguT, bgu, nullptr, hu, 2*FFD, EE, nullptr);
    // 7) out = hu@wd + bd + x1 (fp32)
    mma_gemm<1><<<dim3(EE/128, MM/128), 256, GEMM_SMEM>>>(hu, wdT, bd, x1, out, EE, FFD, nullptr);
}

// round 16
// speedup vs baseline: 1.0761x; 1.0738x over previous
#include <cuda_runtime.h>
#include <cuda_fp16.h>
#include <stdint.h>
#include <math.h>

#define BB  2
#define SS  2048
#define EE  1024
#define HH  16
#define HD_ 64
#define FFD 4096
#define MM  (BB*SS)   // 4096

// ---------------- scratch (allocation-free) ----------------
static __device__ __half g_h    [MM*EE];
static __device__ __half g_q    [MM*EE];      // q, RoPE'd, permuted, scaled by 0.125*log2e
static __device__ __half g_kv   [MM*128];     // packed [k(permuted,roped) | v]
static __device__ __half g_att  [MM*EE];
static __device__ float  g_x1   [MM*EE];
static __device__ __half g_hu   [MM*FFD];
// transposed fp16 weights
static __device__ __half g_wqkvT[1152*EE];
static __device__ __half g_woT  [EE*EE];
static __device__ __half g_wguT [2*FFD*EE];
static __device__ __half g_wdT  [EE*FFD];
static __device__ float  g_bqkv [1152];
static __device__ float  g_bgu  [2*FFD];
static __device__ float2 g_ropetab[SS*32];

// =================== helpers ===================
__device__ __forceinline__ uint32_t smem_u32(const void* p) {
    uint32_t a;
    asm("{ .reg .u64 t; cvta.to.shared.u64 t, %1; cvt.u32.u64 %0, t; }"
        : "=r"(a) : "l"(p));
    return a;
}
__device__ __forceinline__ void cpasync16(uint32_t sp, const void* gp) {
    asm volatile("cp.async.ca.shared.global [%0], [%1], 16;" :: "r"(sp), "l"(gp) : "memory");
}
__device__ __forceinline__ void ldsm4(uint32_t addr, uint32_t& r0, uint32_t& r1,
                                      uint32_t& r2, uint32_t& r3) {
    asm volatile("ldmatrix.sync.aligned.m8n8.x4.shared.b16 {%0,%1,%2,%3}, [%4];"
                 : "=r"(r0), "=r"(r1), "=r"(r2), "=r"(r3) : "r"(addr));
}
__device__ __forceinline__ void ldsm4t(uint32_t addr, uint32_t& r0, uint32_t& r1,
                                       uint32_t& r2, uint32_t& r3) {
    asm volatile("ldmatrix.sync.aligned.m8n8.x4.trans.shared.b16 {%0,%1,%2,%3}, [%4];"
                 : "=r"(r0), "=r"(r1), "=r"(r2), "=r"(r3) : "r"(addr));
}
__device__ __forceinline__ void mma_f16(float* d, const uint32_t* a, const uint32_t* b) {
    asm volatile(
        "mma.sync.aligned.m16n8k16.row.col.f32.f16.f16.f32 "
        "{%0,%1,%2,%3}, {%4,%5,%6,%7}, {%8,%9}, {%0,%1,%2,%3};"
        : "+f"(d[0]), "+f"(d[1]), "+f"(d[2]), "+f"(d[3])
        : "r"(a[0]), "r"(a[1]), "r"(a[2]), "r"(a[3]), "r"(b[0]), "r"(b[1]));
}
__device__ __forceinline__ uint32_t packh2(float a, float b) {
    __half2 h = __floats2half2_rn(a, b);
    return *(uint32_t*)&h;
}
__device__ __forceinline__ float ex2f(float x) {   // 2^x, approx
    float r; asm("ex2.approx.f32 %0, %1;" : "=f"(r) : "f"(x)); return r;
}

// GEMM smem: per stage {A[128][72h] + B[128][72h]} pitch 144 B; 3 stages, K-chunk 64
#define OP_BYTES   18432
#define STAGE_B    (2 * OP_BYTES)     // 36864
#define GEMM_SMEM  (3 * STAGE_B)      // 110592

// =================== fp16 mma.sync GEMM (3-stage, K-chunk 64, 1 sync/chunk) ===========
// EPI: 1=+bias+extra(f32)->f32; 5=QKV split + fused RoPE; 6=fused gelu-gate*up -> hu
template<int EPI>
__global__ void __launch_bounds__(256, 2)
mma_gemm(const __half* __restrict__ A, const __half* __restrict__ WT,
         const float* __restrict__ bias, const void* extra,
         void* __restrict__ Cv, int N, int K, const float2* __restrict__ rope) {
    extern __shared__ char dyn[];
    const uint32_t smem_base = smem_u32(dyn);

    const int tid  = threadIdx.x;
    const int lane = tid & 31;
    const int warp = tid >> 5;
    const int wr = warp & 1;
    const int wc = warp >> 1;
    const int row0 = blockIdx.y * 128, col0 = blockIdx.x * 128;
    const int rp = lane >> 2;
    const int cp = lane & 3;

    const uint32_t a_lm = (uint32_t)((wr*64 + (lane & 15)) * 144 + ((lane >> 4) & 1) * 16);
    const uint32_t b_lm = (uint32_t)((wc*32 + (lane & 7) + ((lane >> 4) & 1) * 8) * 144
                                     + ((lane >> 3) & 1) * 16);

    float acc[4][4][4];
#pragma unroll
    for (int i = 0; i < 4; i++)
#pragma unroll
        for (int j = 0; j < 4; j++)
#pragma unroll
            for (int q = 0; q < 4; q++) acc[i][j][q] = 0.f;

    // chunk = 64 halves (128 B/row): 4 x 16B per thread per operand
    auto issue = [&](int buf, int kb) {
        uint32_t as = smem_base + (uint32_t)buf * STAGE_B;
        uint32_t bs = as + OP_BYTES;
#pragma unroll
        for (int i = 0; i < 4; i++) {
            int f = tid + i * 256;
            int r = f >> 3, c = f & 7;
            cpasync16(as + (uint32_t)(r * 144 + c * 16),
                      A + (size_t)(row0 + r) * K + kb + c * 8);
        }
#pragma unroll
        for (int i = 0; i < 4; i++) {
            int f = tid + i * 256;
            int r = f >> 3, c = f & 7;
            cpasync16(bs + (uint32_t)(r * 144 + c * 16),
                      WT + (size_t)(col0 + r) * K + kb + c * 8);
        }
        asm volatile("cp.async.commit_group;" ::: "memory");
    };

    auto compute = [&](int buf) {
        const uint32_t as = smem_base + (uint32_t)buf * STAGE_B + a_lm;
        const uint32_t bs = smem_base + (uint32_t)buf * STAGE_B + OP_BYTES + b_lm;
#pragma unroll
        for (int ks = 0; ks < 4; ks++) {            // four k16 steps
            uint32_t af[4][4];
#pragma unroll
            for (int mt = 0; mt < 4; mt++)
                ldsm4(as + (uint32_t)(mt * 2304 + ks * 32),
                      af[mt][0], af[mt][1], af[mt][2], af[mt][3]);
            uint32_t bf[4][2];
            ldsm4(bs + (uint32_t)(ks * 32),        bf[0][0], bf[0][1], bf[1][0], bf[1][1]);
            ldsm4(bs + (uint32_t)(2304 + ks * 32), bf[2][0], bf[2][1], bf[3][0], bf[3][1]);
#pragma unroll
            for (int mt = 0; mt < 4; mt++)
#pragma unroll
                for (int nt = 0; nt < 4; nt++)
                    mma_f16(acc[mt][nt], af[mt], bf[nt]);
        }
    };

    const int nk = K >> 6;               // K divisible by 64 for all shapes
    issue(0, 0); issue(1, 64);
    int cur = 0, nxt = 2;
    for (int kt = 0; kt < nk; kt++) {
        if (kt == nk - 1) asm volatile("cp.async.wait_group 0;" ::: "memory");
        else              asm volatile("cp.async.wait_group 1;" ::: "memory");
        __syncthreads();
        if (kt + 2 < nk) { issue(nxt, (kt + 2) << 6); nxt = (nxt == 2) ? 0 : nxt + 1; }
        compute(cur);
        cur = (cur == 2) ? 0 : cur + 1;
    }

    // ---------------- epilogue ----------------
    if (EPI == 6) {
        float* smg = (float*)dyn;                // 128 x 72 fp32 = 36864 B
        __syncthreads();
        if (wc < 2) {
#pragma unroll
            for (int mt = 0; mt < 4; mt++)
#pragma unroll
                for (int nt = 0; nt < 4; nt++) {
                    int rl = wr*64 + mt*16 + rp;
                    int cl = wc*32 + nt*8 + 2*cp;
#pragma unroll
                    for (int half_ = 0; half_ < 2; half_++) {
                        int r = rl + half_ * 8;
                        float v0 = acc[mt][nt][half_*2 + 0] + bias[col0 + cl];
                        float v1 = acc[mt][nt][half_*2 + 1] + bias[col0 + cl + 1];
                        v0 = 0.5f * v0 * (1.0f + erff(v0 * 0.7071067811865476f));
                        v1 = 0.5f * v1 * (1.0f + erff(v1 * 0.7071067811865476f));
                        *(float2*)&smg[r * 72 + cl] = make_float2(v0, v1);
                    }
                }
        }
        __syncthreads();
        if (wc >= 2) {
            __half* hu = (__half*)Cv;
            const int p64 = (col0 >> 7) * 64;
#pragma unroll
            for (int mt = 0; mt < 4; mt++)
#pragma unroll
                for (int nt = 0; nt < 4; nt++) {
                    int rl = wr*64 + mt*16 + rp;
                    int cl = (wc - 2)*32 + nt*8 + 2*cp;
#pragma unroll
                    for (int half_ = 0; half_ < 2; half_++) {
                        int r = rl + half_ * 8;
                        float v0 = acc[mt][nt][half_*2 + 0] + bias[col0 + 64 + cl];
                        float v1 = acc[mt][nt][half_*2 + 1] + bias[col0 + 64 + cl + 1];
                        float2 g = *(const float2*)&smg[r * 72 + cl];
                        *(__half2*)&hu[(size_t)(row0 + r) * FFD + p64 + cl] =
                            __floats2half2_rn(v0 * g.x, v1 * g.y);
                    }
                }
        }
        return;
    }

#pragma unroll
    for (int mt = 0; mt < 4; mt++) {
#pragma unroll
        for (int nt = 0; nt < 4; nt++) {
            int row = row0 + wr*64 + mt*16 + rp;
            int col = col0 + wc*32 + nt*8 + 2*cp;
#pragma unroll
            for (int half_ = 0; half_ < 2; half_++) {
                int r = row + half_ * 8;
                float v0 = acc[mt][nt][half_*2 + 0] + bias[col];
                float v1 = acc[mt][nt][half_*2 + 1] + bias[col + 1];
                if (EPI == 5) {
                    if (col < 1088) {            // q or k: fused RoPE rotation
                        int jj = (col & 63) >> 1;
                        float2 cs = __ldg(&rope[(r & (SS-1)) * 32 + jj]);
                        float o0 = v0 * cs.x - v1 * cs.y;
                        float o1 = v0 * cs.y + v1 * cs.x;
                        if (col < 1024) {        // q: fold 1/8 and log2e for exp2 softmax
                            o0 *= 0.18033688011111793f; o1 *= 0.18033688011111793f;
                        }
                        v0 = o0; v1 = o1;
                    }
                    __half2 o = __floats2half2_rn(v0, v1);
                    if (col < 1024)
                        *(__half2*)((__half*)Cv + (size_t)r * N + col) = o;
                    else
                        *(__half2*)((__half*)extra + (size_t)r * 128 + (col - 1024)) = o;
                } else { // EPI 1
                    size_t gi = (size_t)r * N + col;
                    float2 e = *(const float2*)((const float*)extra + gi);
                    *(float2*)((float*)Cv + gi) = make_float2(v0 + e.x, v1 + e.y);
                }
            }
        }
    }
}

// ---------------- fused weight prep: transposes + rope table + permuted q/k ----------
#define WPREP_BLOCKS 3616
__global__ void __launch_bounds__(256)
wprep_kernel(const float* __restrict__ wq, const float* __restrict__ wk,
             const float* __restrict__ wv, const float* __restrict__ wo,
             const float* __restrict__ wg, const float* __restrict__ wu,
             const float* __restrict__ wd,
             __half* __restrict__ wqkvT, __half* __restrict__ woT,
             __half* __restrict__ wguT, __half* __restrict__ wdT,
             const float* __restrict__ bq, const float* __restrict__ bk,
             const float* __restrict__ bv, const float* __restrict__ bg,
             const float* __restrict__ bu,
             float* __restrict__ bqkv, float* __restrict__ bgu,
             float2* __restrict__ ropetab) {
    const int bidx = blockIdx.x;
    const int tid = threadIdx.x;

    if (bidx == 0) {
#pragma unroll
        for (int j = 0; j < 5; j++) {
            int i = tid + j * 256;
            if (i < 1152) {
                if (i < 1024) {
                    int slot = i & 63;
                    int orig = (slot & 1) ? (slot >> 1) + 32 : (slot >> 1);
                    bqkv[i] = bq[(i & ~63) | orig];
                } else if (i < 1088) {
                    int slot = i - 1024;
                    int orig = (slot & 1) ? (slot >> 1) + 32 : (slot >> 1);
                    bqkv[i] = bk[orig];
                } else {
                    bqkv[i] = bv[i - 1088];
                }
            }
        }
    }
    if (bidx == 1) {
#pragma unroll
        for (int j = 0; j < 32; j++) {
            int i = tid + j * 256;
            int p = i >> 7, r = i & 127;
            bgu[i] = (r < 64) ? bg[p*64 + r] : bu[p*64 + (r - 64)];
        }
    }
    if (bidx >= 2 && bidx < 258) {
        int e = (bidx - 2) * 256 + tid;
        int s = e >> 5, j = e & 31;
        float inv = exp2f((float)j * -0.41524101186092029f);
        float c, sn;
        sincosf((float)s * inv, &sn, &c);
        ropetab[e] = make_float2(c, sn);
    }

    const float* W; __half* WT; int K, N, t, nbase;
    bool qkperm = false;
    if      (bidx < 256)  { W = wq; WT = wqkvT;           K = EE;  N = EE;  t = bidx;        qkperm = true; }
    else if (bidx < 272)  { W = wk; WT = wqkvT + 1024*EE; K = EE;  N = 64;  t = bidx - 256;  qkperm = true; }
    else if (bidx < 288)  { W = wv; WT = wqkvT + 1088*EE; K = EE;  N = 64;  t = bidx - 272;  }
    else if (bidx < 544)  { W = wo; WT = woT;             K = EE;  N = EE;  t = bidx - 288;  }
    else if (bidx < 1568) { W = wg; WT = wguT;            K = EE;  N = FFD; t = bidx - 544;  }
    else if (bidx < 2592) { W = wu; WT = wguT;            K = EE;  N = FFD; t = bidx - 1568; }
    else                  { W = wd; WT = wdT;             K = FFD; N = EE;  t = bidx - 2592; }

    const int tilesX = N >> 6;
    const int nb = (t % tilesX) * 64, kb = (t / tilesX) * 64;
    if (bidx >= 544 && bidx < 1568)       nbase = (nb >> 6) * 128;
    else if (bidx >= 1568 && bidx < 2592) nbase = (nb >> 6) * 128 + 64;
    else                                   nbase = nb;

    __shared__ float sm[64][65];
    const int x = tid & 15, y = tid >> 4;
#pragma unroll
    for (int j = 0; j < 4; j++) {
        int r = y + j * 16;
        float4 v = *(const float4*)&W[(size_t)(kb + r) * N + nb + x * 4];
        sm[x*4 + 0][r] = v.x; sm[x*4 + 1][r] = v.y;
        sm[x*4 + 2][r] = v.z; sm[x*4 + 3][r] = v.w;
    }
    __syncthreads();
    const int lane = tid & 31, w = tid >> 5;
#pragma unroll
    for (int j = 0; j < 8; j++) {
        int n = w * 8 + j;
        int ndst = qkperm ? (((n & 31) << 1) | (n >> 5)) : n;
        __half2 h2 = __floats2half2_rn(sm[n][lane*2], sm[n][lane*2 + 1]);
        *(uint32_t*)&WT[(size_t)(nbase + ndst) * K + kb + lane*2] = *(uint32_t*)&h2;
    }
}

// ---------------- rmsnorm (fp16 output) ----------------
__global__ void rmsnorm_kernel(const float* __restrict__ x, const float* __restrict__ g,
                               __half* __restrict__ out) {
    int row = blockIdx.x;
    const float* xr = x + (size_t)row * EE;
    float v[4];
    float s = 0.f;
#pragma unroll
    for (int i = 0; i < 4; i++) { v[i] = xr[threadIdx.x + i*256]; s += v[i]*v[i]; }
    __shared__ float red[8];
#pragma unroll
    for (int o = 16; o > 0; o >>= 1) s += __shfl_xor_sync(0xffffffffu, s, o);
    if ((threadIdx.x & 31) == 0) red[threadIdx.x >> 5] = s;
    __syncthreads();
    if (threadIdx.x < 8) {
        float t = red[threadIdx.x];
#pragma unroll
        for (int o = 4; o > 0; o >>= 1) t += __shfl_xor_sync(0xffu, t, o);
        if (threadIdx.x == 0) red[0] = t;
    }
    __syncthreads();
    float ms = red[0] * (1.0f / EE);
    float r  = rsqrtf(ms + 1.1920929e-7f);
#pragma unroll
    for (int i = 0; i < 4; i++) {
        int c = threadIdx.x + i*256;
        out[(size_t)row*EE + c] = __float2half_rn(v[i] * r * g[c]);
    }
}

// ---------------- Flash attention: 2 heads per CTA share K/V; log2-domain softmax ------
// scores are pre-scaled by log2e (folded into q), so use ex2 directly.
#define ATT_SMEM 55296
__global__ void __launch_bounds__(256)
attn_mma(const __half* __restrict__ q, const __half* __restrict__ kv,
         __half* __restrict__ out) {
    extern __shared__ char smc[];
    const uint32_t sb = smem_u32(smc);
    const int tid = threadIdx.x, lane = tid & 31, w = tid >> 5;
    const int hh = w >> 2, wq_ = w & 3;
    const int b = (int)(blockIdx.y >> 3), h0 = ((int)blockIdx.y & 7) * 2;
    const int qb = (int)(gridDim.x - 1 - blockIdx.x);
    const int rp = lane >> 2, cp = lane & 3;

    const uint32_t qs = sb + (uint32_t)hh * 9216u;
    const uint32_t a_lm = (uint32_t)((wq_*16 + (lane & 15)) * 144 + ((lane >> 4) & 1) * 16);
    const uint32_t b_lm = (uint32_t)(((lane & 7) + ((lane >> 4) & 1) * 8) * 144
                                     + ((lane >> 3) & 1) * 16);
    const uint32_t v_lm = (uint32_t)(((lane & 7) + ((lane >> 3) & 1) * 8) * 144
                                     + ((lane >> 4) & 1) * 16);

    const __half* qg = q + ((size_t)(b*SS + qb*64)) * 1024;
#pragma unroll
    for (int i = 0; i < 4; i++) {
        int f = tid + i * 256;
        int hx = f >> 9, rem = f & 511;
        int r = rem >> 3, c = rem & 7;
        cpasync16(sb + (uint32_t)(hx * 9216 + r * 144 + c * 16),
                  qg + (size_t)r * 1024 + (h0 + hx) * 64 + c * 8);
    }
    const __half* kg = kv + (size_t)(b*SS) * 128;
    const __half* vg = kg + 64;
    auto issue_kv = [&](int buf, int kb) {
        uint32_t ksm = sb + 18432u + (uint32_t)buf * 18432u;
        uint32_t vsm = ksm + 9216u;
#pragma unroll
        for (int i = 0; i < 2; i++) {
            int f = tid + i * 256;
            int r = f >> 3, c = f & 7;
            size_t gof = (size_t)(kb*64 + r) * 128 + c * 8;
            cpasync16(ksm + (uint32_t)(r * 144 + c * 16), kg + gof);
            cpasync16(vsm + (uint32_t)(r * 144 + c * 16), vg + gof);
        }
        asm volatile("cp.async.commit_group;" ::: "memory");
    };
    issue_kv(0, 0);

    float o[8][4];
#pragma unroll
    for (int nt = 0; nt < 8; nt++)
#pragma unroll
        for (int j = 0; j < 4; j++) o[nt][j] = 0.f;
    float m0 = -1e30f, m1 = -1e30f, l0 = 0.f, l1 = 0.f;
    uint32_t afh[4][4];

    for (int kb = 0; kb <= qb; kb++) {
        int buf = kb & 1;
        if (kb < qb) {
            issue_kv(buf ^ 1, kb + 1);
            asm volatile("cp.async.wait_group 1;" ::: "memory");
        } else {
            asm volatile("cp.async.wait_group 0;" ::: "memory");
        }
        __syncthreads();
        const uint32_t ksm = sb + 18432u + (uint32_t)buf * 18432u;
        const uint32_t vsm = ksm + 9216u;

        if (kb == 0) {
#pragma unroll
            for (int ks = 0; ks < 4; ks++)
                ldsm4(qs + a_lm + (uint32_t)(ks * 32),
                      afh[ks][0], afh[ks][1], afh[ks][2], afh[ks][3]);
        }

        float s[8][4];
#pragma unroll
        for (int nt = 0; nt < 8; nt++)
#pragma unroll
            for (int j = 0; j < 4; j++) s[nt][j] = 0.f;
#pragma unroll
        for (int ks = 0; ks < 4; ks++) {
#pragma unroll
            for (int p2 = 0; p2 < 4; p2++) {
                uint32_t bf[4];
                ldsm4(ksm + b_lm + (uint32_t)(p2 * 16 * 144 + ks * 32),
                      bf[0], bf[1], bf[2], bf[3]);
                mma_f16(s[p2*2],     afh[ks], &bf[0]);
                mma_f16(s[p2*2 + 1], afh[ks], &bf[2]);
            }
        }

        if (kb == qb) {
#pragma unroll
            for (int nt = 0; nt < 8; nt++) {
                int key0 = nt*8 + 2*cp;
                int r0 = wq_*16 + rp, r1 = r0 + 8;
                if (key0     > r0) s[nt][0] = -1e30f;
                if (key0 + 1 > r0) s[nt][1] = -1e30f;
                if (key0     > r1) s[nt][2] = -1e30f;
                if (key0 + 1 > r1) s[nt][3] = -1e30f;
            }
        }

        float mx0 = -1e30f, mx1 = -1e30f;
#pragma unroll
        for (int nt = 0; nt < 8; nt++) {
            mx0 = fmaxf(mx0, fmaxf(s[nt][0], s[nt][1]));
            mx1 = fmaxf(mx1, fmaxf(s[nt][2], s[nt][3]));
        }
        mx0 = fmaxf(mx0, __shfl_xor_sync(0xffffffffu, mx0, 1, 4));
        mx0 = fmaxf(mx0, __shfl_xor_sync(0xffffffffu, mx0, 2, 4));
        mx1 = fmaxf(mx1, __shfl_xor_sync(0xffffffffu, mx1, 1, 4));
        mx1 = fmaxf(mx1, __shfl_xor_sync(0xffffffffu, mx1, 2, 4));
        float mn0 = fmaxf(m0, mx0), mn1 = fmaxf(m1, mx1);
        float al0 = ex2f(m0 - mn0), al1 = ex2f(m1 - mn1);
        float sum0 = 0.f, sum1 = 0.f;
        uint32_t ph[8][2];
#pragma unroll
        for (int nt = 0; nt < 8; nt++) {
            float e0 = ex2f(s[nt][0] - mn0);
            float e1 = ex2f(s[nt][1] - mn0);
            float e2 = ex2f(s[nt][2] - mn1);
            float e3 = ex2f(s[nt][3] - mn1);
            sum0 += e0 + e1; sum1 += e2 + e3;
            ph[nt][0] = packh2(e0, e1);
            ph[nt][1] = packh2(e2, e3);
        }
        sum0 += __shfl_xor_sync(0xffffffffu, sum0, 1, 4);
        sum0 += __shfl_xor_sync(0xffffffffu, sum0, 2, 4);
        sum1 += __shfl_xor_sync(0xffffffffu, sum1, 1, 4);
        sum1 += __shfl_xor_sync(0xffffffffu, sum1, 2, 4);
        l0 = l0 * al0 + sum0; l1 = l1 * al1 + sum1;
        m0 = mn0; m1 = mn1;
#pragma unroll
        for (int nt = 0; nt < 8; nt++) {
            o[nt][0] *= al0; o[nt][1] *= al0;
            o[nt][2] *= al1; o[nt][3] *= al1;
        }

#pragma unroll
        for (int kt = 0; kt < 4; kt++) {
            uint32_t pa[4] = { ph[2*kt][0], ph[2*kt][1], ph[2*kt+1][0], ph[2*kt+1][1] };
#pragma unroll
            for (int np = 0; np < 4; np++) {
                uint32_t bf[4];
                ldsm4t(vsm + v_lm + (uint32_t)(kt * 16 * 144 + np * 32),
                       bf[0], bf[1], bf[2], bf[3]);
                mma_f16(o[np*2],     pa, &bf[0]);
                mma_f16(o[np*2 + 1], pa, &bf[2]);
            }
        }
        __syncthreads();
    }

    float inv0 = 1.0f / l0, inv1 = 1.0f / l1;
    const int r0 = b*SS + qb*64 + wq_*16 + rp;
    const int h = h0 + hh;
#pragma unroll
    for (int nt = 0; nt < 8; nt++) {
        int d = h*64 + nt*8 + 2*cp;
        *(__half2*)&out[(size_t)r0 * 1024 + d] =
            __floats2half2_rn(o[nt][0] * inv0, o[nt][1] * inv0);
        *(__half2*)&out[(size_t)(r0 + 8) * 1024 + d] =
            __floats2half2_rn(o[nt][2] * inv1, o[nt][3] * inv1);
    }
}

// ---------------- launch ----------------
extern "C" void kernel_launch(void* const* d_in, const int* in_sizes, int n_in,
                              void* d_out, int out_size) {
    const float* x  = (const float*)d_in[0];
    const float* wq = (const float*)d_in[1];
    const float* bq = (const float*)d_in[2];
    const float* wk = (const float*)d_in[3];
    const float* bk = (const float*)d_in[4];
    const float* wv = (const float*)d_in[5];
    const float* bv = (const float*)d_in[6];
    const float* wo = (const float*)d_in[7];
    const float* bo = (const float*)d_in[8];
    const float* wg = (const float*)d_in[9];
    const float* bg = (const float*)d_in[10];
    const float* wu = (const float*)d_in[11];
    const float* bu = (const float*)d_in[12];
    const float* wd = (const float*)d_in[13];
    const float* bd = (const float*)d_in[14];
    const float* g1 = (const float*)d_in[15];
    const float* g2 = (const float*)d_in[16];
    float* out = (float*)d_out;

    __half *h, *qb_, *kv, *att, *hu;
    __half *wqkvT, *woT, *wguT, *wdT;
    float *x1, *bqkv, *bgu;
    float2* ropetab;
    cudaGetSymbolAddress((void**)&h,       g_h);
    cudaGetSymbolAddress((void**)&qb_,     g_q);
    cudaGetSymbolAddress((void**)&kv,      g_kv);
    cudaGetSymbolAddress((void**)&att,     g_att);
    cudaGetSymbolAddress((void**)&x1,      g_x1);
    cudaGetSymbolAddress((void**)&hu,      g_hu);
    cudaGetSymbolAddress((void**)&wqkvT,   g_wqkvT);
    cudaGetSymbolAddress((void**)&woT,     g_woT);
    cudaGetSymbolAddress((void**)&wguT,    g_wguT);
    cudaGetSymbolAddress((void**)&wdT,     g_wdT);
    cudaGetSymbolAddress((void**)&bqkv,    g_bqkv);
    cudaGetSymbolAddress((void**)&bgu,     g_bgu);
    cudaGetSymbolAddress((void**)&ropetab, g_ropetab);

    cudaFuncSetAttribute(mma_gemm<1>, cudaFuncAttributeMaxDynamicSharedMemorySize, GEMM_SMEM);
    cudaFuncSetAttribute(mma_gemm<5>, cudaFuncAttributeMaxDynamicSharedMemorySize, GEMM_SMEM);
    cudaFuncSetAttribute(mma_gemm<6>, cudaFuncAttributeMaxDynamicSharedMemorySize, GEMM_SMEM);
    cudaFuncSetAttribute(attn_mma,    cudaFuncAttributeMaxDynamicSharedMemorySize, ATT_SMEM);

    // 0) fused weight prep
    wprep_kernel<<<WPREP_BLOCKS, 256>>>(wq, wk, wv, wo, wg, wu, wd,
                                        wqkvT, woT, wguT, wdT,
                                        bq, bk, bv, bg, bu, bqkv, bgu, ropetab);
    // 1) rmsnorm(x, g1) -> h (fp16)
    rmsnorm_kernel<<<MM, 256>>>(x, g1, h);
    // 2) fused QKV projection + RoPE (q scaled by 0.125*log2e)
    mma_gemm<5><<<dim3(1152/128, MM/128), 256, GEMM_SMEM>>>(h, wqkvT, bqkv, kv, qb_, EE, EE, ropetab);
    // 3) attention (2 heads/CTA, log2-domain softmax)
    attn_mma<<<dim3(SS/64, BB*HH/2), 256, ATT_SMEM>>>(qb_, kv, att);
    // 4) o-proj + residual(x) -> x1 (fp32)
    mma_gemm<1><<<dim3(EE/128, MM/128), 256, GEMM_SMEM>>>(att, woT, bo, x, x1, EE, EE, nullptr);
    // 5) rmsnorm(x1, g2) -> h (fp16)
    rmsnorm_kernel<<<MM, 256>>>(x1, g2, h);
    // 6) fused FFN: hu = fp16(gelu(h@wg+bg) * (h@wu+bu))
    mma_gemm<6><<<dim3(2*FFD/128, MM/128), 256, GEMM_SMEM>>>(h, wguT, bgu, nullptr, hu, 2*FFD, EE, nullptr);
    // 7) out = hu@wd + bd + x1 (fp32)
    mma_gemm<1><<<dim3(EE/128, MM/128), 256, GEMM_SMEM>>>(hu, wdT, bd, x1, out, EE, FFD, nullptr);
}

// round 17
// speedup vs baseline: 1.0802x; 1.0038x over previous
#include <cuda_runtime.h>
#include <cuda_fp16.h>
#include <stdint.h>
#include <math.h>

#define BB  2
#define SS  2048
#define EE  1024
#define HH  16
#define HD_ 64
#define FFD 4096
#define MM  (BB*SS)   // 4096

// ---------------- scratch (allocation-free) ----------------
static __device__ __half g_h    [MM*EE];
static __device__ __half g_q    [MM*EE];      // q, RoPE'd, permuted, scaled by 0.125*log2e
static __device__ __half g_kv   [MM*128];     // packed [k(permuted,roped) | v]
static __device__ __half g_att  [MM*EE];
static __device__ float  g_x1   [MM*EE];
static __device__ __half g_hu   [MM*FFD];
// transposed fp16 weights
static __device__ __half g_wqkvT[1152*EE];
static __device__ __half g_woT  [EE*EE];
static __device__ __half g_wguT [2*FFD*EE];
static __device__ __half g_wdT  [EE*FFD];
static __device__ float  g_bqkv [1152];
static __device__ float  g_bgu  [2*FFD];
static __device__ float2 g_ropetab[SS*32];

// =================== helpers ===================
__device__ __forceinline__ uint32_t smem_u32(const void* p) {
    uint32_t a;
    asm("{ .reg .u64 t; cvta.to.shared.u64 t, %1; cvt.u32.u64 %0, t; }"
        : "=r"(a) : "l"(p));
    return a;
}
__device__ __forceinline__ void cpasync16(uint32_t sp, const void* gp) {
    asm volatile("cp.async.ca.shared.global [%0], [%1], 16;" :: "r"(sp), "l"(gp) : "memory");
}
__device__ __forceinline__ void ldsm4(uint32_t addr, uint32_t& r0, uint32_t& r1,
                                      uint32_t& r2, uint32_t& r3) {
    asm volatile("ldmatrix.sync.aligned.m8n8.x4.shared.b16 {%0,%1,%2,%3}, [%4];"
                 : "=r"(r0), "=r"(r1), "=r"(r2), "=r"(r3) : "r"(addr));
}
__device__ __forceinline__ void ldsm4t(uint32_t addr, uint32_t& r0, uint32_t& r1,
                                       uint32_t& r2, uint32_t& r3) {
    asm volatile("ldmatrix.sync.aligned.m8n8.x4.trans.shared.b16 {%0,%1,%2,%3}, [%4];"
                 : "=r"(r0), "=r"(r1), "=r"(r2), "=r"(r3) : "r"(addr));
}
__device__ __forceinline__ void mma_f16(float* d, const uint32_t* a, const uint32_t* b) {
    asm volatile(
        "mma.sync.aligned.m16n8k16.row.col.f32.f16.f16.f32 "
        "{%0,%1,%2,%3}, {%4,%5,%6,%7}, {%8,%9}, {%0,%1,%2,%3};"
        : "+f"(d[0]), "+f"(d[1]), "+f"(d[2]), "+f"(d[3])
        : "r"(a[0]), "r"(a[1]), "r"(a[2]), "r"(a[3]), "r"(b[0]), "r"(b[1]));
}
__device__ __forceinline__ uint32_t packh2(float a, float b) {
    __half2 h = __floats2half2_rn(a, b);
    return *(uint32_t*)&h;
}
__device__ __forceinline__ float ex2f(float x) {
    float r; asm("ex2.approx.f32 %0, %1;" : "=f"(r) : "f"(x)); return r;
}

// GEMM smem: per stage {A[128][72h] + B[128][72h]} pitch 144 B; 3 stages, K-chunk 64
#define OP_BYTES   18432
#define STAGE_B    (2 * OP_BYTES)     // 36864
#define GEMM_SMEM  (3 * STAGE_B)      // 110592

// =================== fp16 mma.sync GEMM (3-stage, K-chunk 64, 1 sync/chunk) ===========
// EPI: 1=+bias+extra(f32)->f32; 5=QKV split + fused RoPE; 6=fused gelu-gate*up -> hu
template<int EPI>
__global__ void __launch_bounds__(256, 2)
mma_gemm(const __half* __restrict__ A, const __half* __restrict__ WT,
         const float* __restrict__ bias, const void* extra,
         void* __restrict__ Cv, int N, int K, const float2* __restrict__ rope) {
    extern __shared__ char dyn[];
    const uint32_t smem_base = smem_u32(dyn);

    const int tid  = threadIdx.x;
    const int lane = tid & 31;
    const int warp = tid >> 5;
    const int wr = warp & 1;
    const int wc = warp >> 1;
    const int row0 = blockIdx.y * 128, col0 = blockIdx.x * 128;
    const int rp = lane >> 2;
    const int cp = lane & 3;

    const uint32_t a_lm = (uint32_t)((wr*64 + (lane & 15)) * 144 + ((lane >> 4) & 1) * 16);
    const uint32_t b_lm = (uint32_t)((wc*32 + (lane & 7) + ((lane >> 4) & 1) * 8) * 144
                                     + ((lane >> 3) & 1) * 16);

    float acc[4][4][4];
#pragma unroll
    for (int i = 0; i < 4; i++)
#pragma unroll
        for (int j = 0; j < 4; j++)
#pragma unroll
            for (int q = 0; q < 4; q++) acc[i][j][q] = 0.f;

    auto issue = [&](int buf, int kb) {
        uint32_t as = smem_base + (uint32_t)buf * STAGE_B;
        uint32_t bs = as + OP_BYTES;
#pragma unroll
        for (int i = 0; i < 4; i++) {
            int f = tid + i * 256;
            int r = f >> 3, c = f & 7;
            cpasync16(as + (uint32_t)(r * 144 + c * 16),
                      A + (size_t)(row0 + r) * K + kb + c * 8);
        }
#pragma unroll
        for (int i = 0; i < 4; i++) {
            int f = tid + i * 256;
            int r = f >> 3, c = f & 7;
            cpasync16(bs + (uint32_t)(r * 144 + c * 16),
                      WT + (size_t)(col0 + r) * K + kb + c * 8);
        }
        asm volatile("cp.async.commit_group;" ::: "memory");
    };

    auto compute = [&](int buf) {
        const uint32_t as = smem_base + (uint32_t)buf * STAGE_B + a_lm;
        const uint32_t bs = smem_base + (uint32_t)buf * STAGE_B + OP_BYTES + b_lm;
#pragma unroll
        for (int ks = 0; ks < 4; ks++) {
            uint32_t af[4][4];
#pragma unroll
            for (int mt = 0; mt < 4; mt++)
                ldsm4(as + (uint32_t)(mt * 2304 + ks * 32),
                      af[mt][0], af[mt][1], af[mt][2], af[mt][3]);
            uint32_t bf[4][2];
            ldsm4(bs + (uint32_t)(ks * 32),        bf[0][0], bf[0][1], bf[1][0], bf[1][1]);
            ldsm4(bs + (uint32_t)(2304 + ks * 32), bf[2][0], bf[2][1], bf[3][0], bf[3][1]);
#pragma unroll
            for (int mt = 0; mt < 4; mt++)
#pragma unroll
                for (int nt = 0; nt < 4; nt++)
                    mma_f16(acc[mt][nt], af[mt], bf[nt]);
        }
    };

    const int nk = K >> 6;
    issue(0, 0); issue(1, 64);
    int cur = 0, nxt = 2;
    for (int kt = 0; kt < nk; kt++) {
        if (kt == nk - 1) asm volatile("cp.async.wait_group 0;" ::: "memory");
        else              asm volatile("cp.async.wait_group 1;" ::: "memory");
        __syncthreads();
        if (kt + 2 < nk) { issue(nxt, (kt + 2) << 6); nxt = (nxt == 2) ? 0 : nxt + 1; }
        compute(cur);
        cur = (cur == 2) ? 0 : cur + 1;
    }

    // ---------------- epilogue ----------------
    if (EPI == 6) {
        float* smg = (float*)dyn;
        __syncthreads();
        if (wc < 2) {
#pragma unroll
            for (int mt = 0; mt < 4; mt++)
#pragma unroll
                for (int nt = 0; nt < 4; nt++) {
                    int rl = wr*64 + mt*16 + rp;
                    int cl = wc*32 + nt*8 + 2*cp;
#pragma unroll
                    for (int half_ = 0; half_ < 2; half_++) {
                        int r = rl + half_ * 8;
                        float v0 = acc[mt][nt][half_*2 + 0] + bias[col0 + cl];
                        float v1 = acc[mt][nt][half_*2 + 1] + bias[col0 + cl + 1];
                        v0 = 0.5f * v0 * (1.0f + erff(v0 * 0.7071067811865476f));
                        v1 = 0.5f * v1 * (1.0f + erff(v1 * 0.7071067811865476f));
                        *(float2*)&smg[r * 72 + cl] = make_float2(v0, v1);
                    }
                }
        }
        __syncthreads();
        if (wc >= 2) {
            __half* hu = (__half*)Cv;
            const int p64 = (col0 >> 7) * 64;
#pragma unroll
            for (int mt = 0; mt < 4; mt++)
#pragma unroll
                for (int nt = 0; nt < 4; nt++) {
                    int rl = wr*64 + mt*16 + rp;
                    int cl = (wc - 2)*32 + nt*8 + 2*cp;
#pragma unroll
                    for (int half_ = 0; half_ < 2; half_++) {
                        int r = rl + half_ * 8;
                        float v0 = acc[mt][nt][half_*2 + 0] + bias[col0 + 64 + cl];
                        float v1 = acc[mt][nt][half_*2 + 1] + bias[col0 + 64 + cl + 1];
                        float2 g = *(const float2*)&smg[r * 72 + cl];
                        *(__half2*)&hu[(size_t)(row0 + r) * FFD + p64 + cl] =
                            __floats2half2_rn(v0 * g.x, v1 * g.y);
                    }
                }
        }
        return;
    }

#pragma unroll
    for (int mt = 0; mt < 4; mt++) {
#pragma unroll
        for (int nt = 0; nt < 4; nt++) {
            int row = row0 + wr*64 + mt*16 + rp;
            int col = col0 + wc*32 + nt*8 + 2*cp;
#pragma unroll
            for (int half_ = 0; half_ < 2; half_++) {
                int r = row + half_ * 8;
                float v0 = acc[mt][nt][half_*2 + 0] + bias[col];
                float v1 = acc[mt][nt][half_*2 + 1] + bias[col + 1];
                if (EPI == 5) {
                    if (col < 1088) {
                        int jj = (col & 63) >> 1;
                        float2 cs = __ldg(&rope[(r & (SS-1)) * 32 + jj]);
                        float o0 = v0 * cs.x - v1 * cs.y;
                        float o1 = v0 * cs.y + v1 * cs.x;
                        if (col < 1024) {
                            o0 *= 0.18033688011111793f; o1 *= 0.18033688011111793f;
                        }
                        v0 = o0; v1 = o1;
                    }
                    __half2 o = __floats2half2_rn(v0, v1);
                    if (col < 1024)
                        *(__half2*)((__half*)Cv + (size_t)r * N + col) = o;
                    else
                        *(__half2*)((__half*)extra + (size_t)r * 128 + (col - 1024)) = o;
                } else { // EPI 1
                    size_t gi = (size_t)r * N + col;
                    float2 e = *(const float2*)((const float*)extra + gi);
                    *(float2*)((float*)Cv + gi) = make_float2(v0 + e.x, v1 + e.y);
                }
            }
        }
    }
}

// ---------------- fused weight prep ----------------
#define WPREP_BLOCKS 3616
__global__ void __launch_bounds__(256)
wprep_kernel(const float* __restrict__ wq, const float* __restrict__ wk,
             const float* __restrict__ wv, const float* __restrict__ wo,
             const float* __restrict__ wg, const float* __restrict__ wu,
             const float* __restrict__ wd,
             __half* __restrict__ wqkvT, __half* __restrict__ woT,
             __half* __restrict__ wguT, __half* __restrict__ wdT,
             const float* __restrict__ bq, const float* __restrict__ bk,
             const float* __restrict__ bv, const float* __restrict__ bg,
             const float* __restrict__ bu,
             float* __restrict__ bqkv, float* __restrict__ bgu,
             float2* __restrict__ ropetab) {
    const int bidx = blockIdx.x;
    const int tid = threadIdx.x;

    if (bidx == 0) {
#pragma unroll
        for (int j = 0; j < 5; j++) {
            int i = tid + j * 256;
            if (i < 1152) {
                if (i < 1024) {
                    int slot = i & 63;
                    int orig = (slot & 1) ? (slot >> 1) + 32 : (slot >> 1);
                    bqkv[i] = bq[(i & ~63) | orig];
                } else if (i < 1088) {
                    int slot = i - 1024;
                    int orig = (slot & 1) ? (slot >> 1) + 32 : (slot >> 1);
                    bqkv[i] = bk[orig];
                } else {
                    bqkv[i] = bv[i - 1088];
                }
            }
        }
    }
    if (bidx == 1) {
#pragma unroll
        for (int j = 0; j < 32; j++) {
            int i = tid + j * 256;
            int p = i >> 7, r = i & 127;
            bgu[i] = (r < 64) ? bg[p*64 + r] : bu[p*64 + (r - 64)];
        }
    }
    if (bidx >= 2 && bidx < 258) {
        int e = (bidx - 2) * 256 + tid;
        int s = e >> 5, j = e & 31;
        float inv = exp2f((float)j * -0.41524101186092029f);
        float c, sn;
        sincosf((float)s * inv, &sn, &c);
        ropetab[e] = make_float2(c, sn);
    }

    const float* W; __half* WT; int K, N, t, nbase;
    bool qkperm = false;
    if      (bidx < 256)  { W = wq; WT = wqkvT;           K = EE;  N = EE;  t = bidx;        qkperm = true; }
    else if (bidx < 272)  { W = wk; WT = wqkvT + 1024*EE; K = EE;  N = 64;  t = bidx - 256;  qkperm = true; }
    else if (bidx < 288)  { W = wv; WT = wqkvT + 1088*EE; K = EE;  N = 64;  t = bidx - 272;  }
    else if (bidx < 544)  { W = wo; WT = woT;             K = EE;  N = EE;  t = bidx - 288;  }
    else if (bidx < 1568) { W = wg; WT = wguT;            K = EE;  N = FFD; t = bidx - 544;  }
    else if (bidx < 2592) { W = wu; WT = wguT;            K = EE;  N = FFD; t = bidx - 1568; }
    else                  { W = wd; WT = wdT;             K = FFD; N = EE;  t = bidx - 2592; }

    const int tilesX = N >> 6;
    const int nb = (t % tilesX) * 64, kb = (t / tilesX) * 64;
    if (bidx >= 544 && bidx < 1568)       nbase = (nb >> 6) * 128;
    else if (bidx >= 1568 && bidx < 2592) nbase = (nb >> 6) * 128 + 64;
    else                                   nbase = nb;

    __shared__ float sm[64][65];
    const int x = tid & 15, y = tid >> 4;
#pragma unroll
    for (int j = 0; j < 4; j++) {
        int r = y + j * 16;
        float4 v = *(const float4*)&W[(size_t)(kb + r) * N + nb + x * 4];
        sm[x*4 + 0][r] = v.x; sm[x*4 + 1][r] = v.y;
        sm[x*4 + 2][r] = v.z; sm[x*4 + 3][r] = v.w;
    }
    __syncthreads();
    const int lane = tid & 31, w = tid >> 5;
#pragma unroll
    for (int j = 0; j < 8; j++) {
        int n = w * 8 + j;
        int ndst = qkperm ? (((n & 31) << 1) | (n >> 5)) : n;
        __half2 h2 = __floats2half2_rn(sm[n][lane*2], sm[n][lane*2 + 1]);
        *(uint32_t*)&WT[(size_t)(nbase + ndst) * K + kb + lane*2] = *(uint32_t*)&h2;
    }
}

// ---------------- rmsnorm (fp16 output) ----------------
__global__ void rmsnorm_kernel(const float* __restrict__ x, const float* __restrict__ g,
                               __half* __restrict__ out) {
    int row = blockIdx.x;
    const float* xr = x + (size_t)row * EE;
    float v[4];
    float s = 0.f;
#pragma unroll
    for (int i = 0; i < 4; i++) { v[i] = xr[threadIdx.x + i*256]; s += v[i]*v[i]; }
    __shared__ float red[8];
#pragma unroll
    for (int o = 16; o > 0; o >>= 1) s += __shfl_xor_sync(0xffffffffu, s, o);
    if ((threadIdx.x & 31) == 0) red[threadIdx.x >> 5] = s;
    __syncthreads();
    if (threadIdx.x < 8) {
        float t = red[threadIdx.x];
#pragma unroll
        for (int o = 4; o > 0; o >>= 1) t += __shfl_xor_sync(0xffu, t, o);
        if (threadIdx.x == 0) red[0] = t;
    }
    __syncthreads();
    float ms = red[0] * (1.0f / EE);
    float r  = rsqrtf(ms + 1.1920929e-7f);
#pragma unroll
    for (int i = 0; i < 4; i++) {
        int c = threadIdx.x + i*256;
        out[(size_t)row*EE + c] = __float2half_rn(v[i] * r * g[c]);
    }
}

// ---------------- Flash attention: 2 heads/CTA, 3 KV buffers, 1 sync per tile ----------
// smem: qs[2][64][144B] @0 (18432); 3 kv bufs @18432 + buf*18432 (9216 k + 9216 v) = 73728
#define ATT_SMEM 73728
__global__ void __launch_bounds__(256)
attn_mma(const __half* __restrict__ q, const __half* __restrict__ kv,
         __half* __restrict__ out) {
    extern __shared__ char smc[];
    const uint32_t sb = smem_u32(smc);
    const int tid = threadIdx.x, lane = tid & 31, w = tid >> 5;
    const int hh = w >> 2, wq_ = w & 3;
    const int b = (int)(blockIdx.y >> 3), h0 = ((int)blockIdx.y & 7) * 2;
    const int qb = (int)(gridDim.x - 1 - blockIdx.x);
    const int rp = lane >> 2, cp = lane & 3;

    const uint32_t qs = sb + (uint32_t)hh * 9216u;
    const uint32_t a_lm = (uint32_t)((wq_*16 + (lane & 15)) * 144 + ((lane >> 4) & 1) * 16);
    const uint32_t b_lm = (uint32_t)(((lane & 7) + ((lane >> 4) & 1) * 8) * 144
                                     + ((lane >> 3) & 1) * 16);
    const uint32_t v_lm = (uint32_t)(((lane & 7) + ((lane >> 3) & 1) * 8) * 144
                                     + ((lane >> 4) & 1) * 16);

    // Q loads join group 0 (committed with first issue_kv)
    const __half* qg = q + ((size_t)(b*SS + qb*64)) * 1024;
#pragma unroll
    for (int i = 0; i < 4; i++) {
        int f = tid + i * 256;
        int hx = f >> 9, rem = f & 511;
        int r = rem >> 3, c = rem & 7;
        cpasync16(sb + (uint32_t)(hx * 9216 + r * 144 + c * 16),
                  qg + (size_t)r * 1024 + (h0 + hx) * 64 + c * 8);
    }
    const __half* kg = kv + (size_t)(b*SS) * 128;
    const __half* vg = kg + 64;
    auto issue_kv = [&](int buf, int kb) {
        uint32_t ksm = sb + 18432u + (uint32_t)buf * 18432u;
        uint32_t vsm = ksm + 9216u;
#pragma unroll
        for (int i = 0; i < 2; i++) {
            int f = tid + i * 256;
            int r = f >> 3, c = f & 7;
            size_t gof = (size_t)(kb*64 + r) * 128 + c * 8;
            cpasync16(ksm + (uint32_t)(r * 144 + c * 16), kg + gof);
            cpasync16(vsm + (uint32_t)(r * 144 + c * 16), vg + gof);
        }
        asm volatile("cp.async.commit_group;" ::: "memory");
    };
    issue_kv(0, 0);
    if (qb >= 1) issue_kv(1, 1);

    float o[8][4];
#pragma unroll
    for (int nt = 0; nt < 8; nt++)
#pragma unroll
        for (int j = 0; j < 4; j++) o[nt][j] = 0.f;
    float m0 = -1e30f, m1 = -1e30f, l0 = 0.f, l1 = 0.f;
    uint32_t afh[4][4];
    int cur = 0, nxt = 2;

    for (int kb = 0; kb <= qb; kb++) {
        if (kb < qb) asm volatile("cp.async.wait_group 1;" ::: "memory");
        else         asm volatile("cp.async.wait_group 0;" ::: "memory");
        __syncthreads();   // publishes tile kb; proves compute(kb-1) done -> buf (kb+2)%3 free
        if (kb + 2 <= qb) { issue_kv(nxt, kb + 2); nxt = (nxt == 2) ? 0 : nxt + 1; }
        const uint32_t ksm = sb + 18432u + (uint32_t)cur * 18432u;
        const uint32_t vsm = ksm + 9216u;
        cur = (cur == 2) ? 0 : cur + 1;

        if (kb == 0) {
#pragma unroll
            for (int ks = 0; ks < 4; ks++)
                ldsm4(qs + a_lm + (uint32_t)(ks * 32),
                      afh[ks][0], afh[ks][1], afh[ks][2], afh[ks][3]);
        }

        float s[8][4];
#pragma unroll
        for (int nt = 0; nt < 8; nt++)
#pragma unroll
            for (int j = 0; j < 4; j++) s[nt][j] = 0.f;
#pragma unroll
        for (int ks = 0; ks < 4; ks++) {
#pragma unroll
            for (int p2 = 0; p2 < 4; p2++) {
                uint32_t bf[4];
                ldsm4(ksm + b_lm + (uint32_t)(p2 * 16 * 144 + ks * 32),
                      bf[0], bf[1], bf[2], bf[3]);
                mma_f16(s[p2*2],     afh[ks], &bf[0]);
                mma_f16(s[p2*2 + 1], afh[ks], &bf[2]);
            }
        }

        if (kb == qb) {
#pragma unroll
            for (int nt = 0; nt < 8; nt++) {
                int key0 = nt*8 + 2*cp;
                int r0 = wq_*16 + rp, r1 = r0 + 8;
                if (key0     > r0) s[nt][0] = -1e30f;
                if (key0 + 1 > r0) s[nt][1] = -1e30f;
                if (key0     > r1) s[nt][2] = -1e30f;
                if (key0 + 1 > r1) s[nt][3] = -1e30f;
            }
        }

        float mx0 = -1e30f, mx1 = -1e30f;
#pragma unroll
        for (int nt = 0; nt < 8; nt++) {
            mx0 = fmaxf(mx0, fmaxf(s[nt][0], s[nt][1]));
            mx1 = fmaxf(mx1, fmaxf(s[nt][2], s[nt][3]));
        }
        mx0 = fmaxf(mx0, __shfl_xor_sync(0xffffffffu, mx0, 1, 4));
        mx0 = fmaxf(mx0, __shfl_xor_sync(0xffffffffu, mx0, 2, 4));
        mx1 = fmaxf(mx1, __shfl_xor_sync(0xffffffffu, mx1, 1, 4));
        mx1 = fmaxf(mx1, __shfl_xor_sync(0xffffffffu, mx1, 2, 4));
        float mn0 = fmaxf(m0, mx0), mn1 = fmaxf(m1, mx1);
        float al0 = ex2f(m0 - mn0), al1 = ex2f(m1 - mn1);
        float sum0 = 0.f, sum1 = 0.f;
        uint32_t ph[8][2];
#pragma unroll
        for (int nt = 0; nt < 8; nt++) {
            float e0 = ex2f(s[nt][0] - mn0);
            float e1 = ex2f(s[nt][1] - mn0);
            float e2 = ex2f(s[nt][2] - mn1);
            float e3 = ex2f(s[nt][3] - mn1);
            sum0 += e0 + e1; sum1 += e2 + e3;
            ph[nt][0] = packh2(e0, e1);
            ph[nt][1] = packh2(e2, e3);
        }
        sum0 += __shfl_xor_sync(0xffffffffu, sum0, 1, 4);
        sum0 += __shfl_xor_sync(0xffffffffu, sum0, 2, 4);
        sum1 += __shfl_xor_sync(0xffffffffu, sum1, 1, 4);
        sum1 += __shfl_xor_sync(0xffffffffu, sum1, 2, 4);
        l0 = l0 * al0 + sum0; l1 = l1 * al1 + sum1;
        m0 = mn0; m1 = mn1;
#pragma unroll
        for (int nt = 0; nt < 8; nt++) {
            o[nt][0] *= al0; o[nt][1] *= al0;
            o[nt][2] *= al1; o[nt][3] *= al1;
        }

#pragma unroll
        for (int kt = 0; kt < 4; kt++) {
            uint32_t pa[4] = { ph[2*kt][0], ph[2*kt][1], ph[2*kt+1][0], ph[2*kt+1][1] };
#pragma unroll
            for (int np = 0; np < 4; np++) {
                uint32_t bf[4];
                ldsm4t(vsm + v_lm + (uint32_t)(kt * 16 * 144 + np * 32),
                       bf[0], bf[1], bf[2], bf[3]);
                mma_f16(o[np*2],     pa, &bf[0]);
                mma_f16(o[np*2 + 1], pa, &bf[2]);
            }
        }
    }

    float inv0 = 1.0f / l0, inv1 = 1.0f / l1;
    const int r0 = b*SS + qb*64 + wq_*16 + rp;
    const int h = h0 + hh;
#pragma unroll
    for (int nt = 0; nt < 8; nt++) {
        int d = h*64 + nt*8 + 2*cp;
        *(__half2*)&out[(size_t)r0 * 1024 + d] =
            __floats2half2_rn(o[nt][0] * inv0, o[nt][1] * inv0);
        *(__half2*)&out[(size_t)(r0 + 8) * 1024 + d] =
            __floats2half2_rn(o[nt][2] * inv1, o[nt][3] * inv1);
    }
}

// ---------------- launch ----------------
extern "C" void kernel_launch(void* const* d_in, const int* in_sizes, int n_in,
                              void* d_out, int out_size) {
    const float* x  = (const float*)d_in[0];
    const float* wq = (const float*)d_in[1];
    const float* bq = (const float*)d_in[2];
    const float* wk = (const float*)d_in[3];
    const float* bk = (const float*)d_in[4];
    const float* wv = (const float*)d_in[5];
    const float* bv = (const float*)d_in[6];
    const float* wo = (const float*)d_in[7];
    const float* bo = (const float*)d_in[8];
    const float* wg = (const float*)d_in[9];
    const float* bg = (const float*)d_in[10];
    const float* wu = (const float*)d_in[11];
    const float* bu = (const float*)d_in[12];
    const float* wd = (const float*)d_in[13];
    const float* bd = (const float*)d_in[14];
    const float* g1 = (const float*)d_in[15];
    const float* g2 = (const float*)d_in[16];
    float* out = (float*)d_out;

    __half *h, *qb_, *kv, *att, *hu;
    __half *wqkvT, *woT, *wguT, *wdT;
    float *x1, *bqkv, *bgu;
    float2* ropetab;
    cudaGetSymbolAddress((void**)&h,       g_h);
    cudaGetSymbolAddress((void**)&qb_,     g_q);
    cudaGetSymbolAddress((void**)&kv,      g_kv);
    cudaGetSymbolAddress((void**)&att,     g_att);
    cudaGetSymbolAddress((void**)&x1,      g_x1);
    cudaGetSymbolAddress((void**)&hu,      g_hu);
    cudaGetSymbolAddress((void**)&wqkvT,   g_wqkvT);
    cudaGetSymbolAddress((void**)&woT,     g_woT);
    cudaGetSymbolAddress((void**)&wguT,    g_wguT);
    cudaGetSymbolAddress((void**)&wdT,     g_wdT);
    cudaGetSymbolAddress((void**)&bqkv,    g_bqkv);
    cudaGetSymbolAddress((void**)&bgu,     g_bgu);
    cudaGetSymbolAddress((void**)&ropetab, g_ropetab);

    cudaFuncSetAttribute(mma_gemm<1>, cudaFuncAttributeMaxDynamicSharedMemorySize, GEMM_SMEM);
    cudaFuncSetAttribute(mma_gemm<5>, cudaFuncAttributeMaxDynamicSharedMemorySize, GEMM_SMEM);
    cudaFuncSetAttribute(mma_gemm<6>, cudaFuncAttributeMaxDynamicSharedMemorySize, GEMM_SMEM);
    cudaFuncSetAttribute(attn_mma,    cudaFuncAttributeMaxDynamicSharedMemorySize, ATT_SMEM);

    // 0) fused weight prep
    wprep_kernel<<<WPREP_BLOCKS, 256>>>(wq, wk, wv, wo, wg, wu, wd,
                                        wqkvT, woT, wguT, wdT,
                                        bq, bk, bv, bg, bu, bqkv, bgu, ropetab);
    // 1) rmsnorm(x, g1) -> h (fp16)
    rmsnorm_kernel<<<MM, 256>>>(x, g1, h);
    // 2) fused QKV projection + RoPE (q scaled by 0.125*log2e)
    mma_gemm<5><<<dim3(1152/128, MM/128), 256, GEMM_SMEM>>>(h, wqkvT, bqkv, kv, qb_, EE, EE, ropetab);
    // 3) attention (2 heads/CTA, 3-buffer single-sync, log2-domain softmax)
    attn_mma<<<dim3(SS/64, BB*HH/2), 256, ATT_SMEM>>>(qb_, kv, att);
    // 4) o-proj + residual(x) -> x1 (fp32)
    mma_gemm<1><<<dim3(EE/128, MM/128), 256, GEMM_SMEM>>>(att, woT, bo, x, x1, EE, EE, nullptr);
    // 5) rmsnorm(x1, g2) -> h (fp16)
    rmsnorm_kernel<<<MM, 256>>>(x1, g2, h);
    // 6) fused FFN: hu = fp16(gelu(h@wg+bg) * (h@wu+bu))
    mma_gemm<6><<<dim3(2*FFD/128, MM/128), 256, GEMM_SMEM>>>(h, wguT, bgu, nullptr, hu, 2*FFD, EE, nullptr);
    // 7) out = hu@wd + bd + x1 (fp32)
    mma_gemm<1><<<dim3(EE/128, MM/128), 256, GEMM_SMEM>>>(hu, wdT, bd, x1, out, EE, FFD, nullptr);
}